// round 4
// baseline (speedup 1.0000x reference)
#include <cuda_runtime.h>
#include <math.h>

#define NB 8
#define CC 1024
#define WW 1024
#define HH 16
#define DD 64
#define QT 128
#define KT 128

typedef unsigned long long ull;

// ---- packed f32x2 helpers (sm_103a FFMA2 path; ptxas never auto-emits) ----
__device__ __forceinline__ void ffma2(ull& d, ull a, ull b) {
    asm("fma.rn.f32x2 %0, %1, %2, %0;" : "+l"(d) : "l"(a), "l"(b));
}
__device__ __forceinline__ void fmul2(ull& d, ull a) {
    asm("mul.rn.f32x2 %0, %0, %1;" : "+l"(d) : "l"(a));
}
__device__ __forceinline__ ull pk2(float lo, float hi) {
    ull r; asm("mov.b64 %0, {%1, %2};" : "=l"(r) : "f"(lo), "f"(hi)); return r;
}
__device__ __forceinline__ ull dup2(float x) { return pk2(x, x); }
__device__ __forceinline__ float2 upk2(ull v) {
    float2 r; asm("mov.b64 {%0, %1}, %2;" : "=f"(r.x), "=f"(r.y) : "l"(v)); return r;
}

// Scratch for Q, K, V projections, each [N, C, W] fp32 (32 MB each).
__device__ float g_q[NB * CC * WW];
__device__ float g_k[NB * CC * WW];
__device__ float g_v[NB * CC * WW];

// ---------------------------------------------------------------------------
// Kernel 1: fused QKV projection, 128x128x16 tiles, FFMA2 inner product.
// ---------------------------------------------------------------------------
__global__ __launch_bounds__(256, 2) void qkv_kernel(
    const float* __restrict__ hid,
    const float* __restrict__ wq, const float* __restrict__ bq,
    const float* __restrict__ wk, const float* __restrict__ bk,
    const float* __restrict__ wv, const float* __restrict__ bv)
{
    const int z = blockIdx.z;
    const int n = z / 3;
    const int p = z - 3 * n;

    const float* __restrict__ A;
    const float* __restrict__ bias;
    float* __restrict__ out;
    if (p == 0)      { A = wq; bias = bq; out = g_q; }
    else if (p == 1) { A = wk; bias = bk; out = g_k; }
    else             { A = wv; bias = bv; out = g_v; }

    const float* __restrict__ B = hid + (size_t)n * CC * WW;
    out += (size_t)n * CC * WW;

    const int m0 = blockIdx.y * 128;
    const int w0 = blockIdx.x * 128;

    __shared__ float As[16][128];
    __shared__ float Bs[16][128];

    const int tid = threadIdx.x;
    const int tx = tid % 16;
    const int ty = tid / 16;

    ull acc2[8][4];
#pragma unroll
    for (int i = 0; i < 8; i++)
#pragma unroll
        for (int j = 0; j < 4; j++) acc2[i][j] = 0ull;

    const int am  = tid % 128;
    const int ak4 = tid / 128;
    const int br  = tid / 32;
    const int bc4 = tid % 32;

    for (int kt = 0; kt < CC; kt += 16) {
        float4 a0 = *(const float4*)&A[(size_t)(m0 + am) * CC + kt + ak4 * 4];
        float4 a1 = *(const float4*)&A[(size_t)(m0 + am) * CC + kt + (ak4 + 2) * 4];
        As[ak4 * 4 + 0][am] = a0.x; As[ak4 * 4 + 1][am] = a0.y;
        As[ak4 * 4 + 2][am] = a0.z; As[ak4 * 4 + 3][am] = a0.w;
        As[(ak4 + 2) * 4 + 0][am] = a1.x; As[(ak4 + 2) * 4 + 1][am] = a1.y;
        As[(ak4 + 2) * 4 + 2][am] = a1.z; As[(ak4 + 2) * 4 + 3][am] = a1.w;

        float4 b0 = *(const float4*)&B[(size_t)(kt + br) * WW + w0 + bc4 * 4];
        float4 b1 = *(const float4*)&B[(size_t)(kt + br + 8) * WW + w0 + bc4 * 4];
        *(float4*)&Bs[br][bc4 * 4]     = b0;
        *(float4*)&Bs[br + 8][bc4 * 4] = b1;

        __syncthreads();

#pragma unroll
        for (int k = 0; k < 16; k++) {
            float4 alo = *(const float4*)&As[k][ty * 4];
            float4 ahi = *(const float4*)&As[k][64 + ty * 4];
            float4 blo = *(const float4*)&Bs[k][tx * 4];
            float4 bhi = *(const float4*)&Bs[k][64 + tx * 4];
            ull b2[4] = { pk2(blo.x, blo.y), pk2(blo.z, blo.w),
                          pk2(bhi.x, bhi.y), pk2(bhi.z, bhi.w) };
            float ar[8] = {alo.x, alo.y, alo.z, alo.w, ahi.x, ahi.y, ahi.z, ahi.w};
#pragma unroll
            for (int i = 0; i < 8; i++) {
                ull a2 = dup2(ar[i]);
#pragma unroll
                for (int j = 0; j < 4; j++) ffma2(acc2[i][j], a2, b2[j]);
            }
        }
        __syncthreads();
    }

#pragma unroll
    for (int i = 0; i < 8; i++) {
        int m = (i < 4) ? (m0 + ty * 4 + i) : (m0 + 64 + ty * 4 + (i - 4));
        float bv_ = bias[m];
        float2 u0 = upk2(acc2[i][0]), u1 = upk2(acc2[i][1]);
        float2 u2 = upk2(acc2[i][2]), u3 = upk2(acc2[i][3]);
        float4 olo = {u0.x + bv_, u0.y + bv_, u1.x + bv_, u1.y + bv_};
        float4 ohi = {u2.x + bv_, u2.y + bv_, u3.x + bv_, u3.y + bv_};
        *(float4*)&out[(size_t)m * WW + w0 + tx * 4]      = olo;
        *(float4*)&out[(size_t)m * WW + w0 + 64 + tx * 4] = ohi;
    }
}

// ---------------------------------------------------------------------------
// Kernel 2: flash attention, CTA = 128q x 128k tile, 8x8 per-thread, FFMA2.
// smem (dynamic, ~101 KB): Qs[64][128] | Ks[64][128] (aliased by Ps[128][64])
//                          | Vs[64][132] | Ms[1024]
// S-gemm packs accumulators along q (pairs free from float4 Q loads).
// PV packs along k (dot-product style): P via LDS.64 pairs, V via LDS.64 from
// natural [d][k] layout; horizontal add once at the very end.
// ---------------------------------------------------------------------------
#define SMEM_FLOATS (8192 + 8192 + 64 * 132 + 1024)

__global__ __launch_bounds__(256, 1) void attn_kernel(
    const float* __restrict__ mask, float* __restrict__ out)
{
    extern __shared__ float sm[];
    float* Qs = sm;                      // [64][128]
    float* Ks = sm + 8192;               // [64][128]
    float* Ps = Ks;                      // alias: [128][64]
    float* Vs = sm + 16384;              // [64][132]
    float* Ms = sm + 16384 + 64 * 132;   // [1024]

    const int qb = blockIdx.x;
    const int nh = blockIdx.y;
    const int n = nh / HH;
    const int h = nh - n * HH;
    const int q0 = qb * QT;

    const float* __restrict__ Qg = g_q + ((size_t)n * CC + h * DD) * WW;
    const float* __restrict__ Kg = g_k + ((size_t)n * CC + h * DD) * WW;
    const float* __restrict__ Vg = g_v + ((size_t)n * CC + h * DD) * WW;

    const int tid = threadIdx.x;
    const int tx = tid & 15;
    const int ty = tid >> 4;
    const int lr = tid >> 5;     // loader row
    const int lc = tid & 31;     // loader float4 col

    // Load Q tile [d][q] (no transpose needed: scratch is channel-major) + mask row
#pragma unroll
    for (int it = 0; it < 8; it++) {
        int d = lr + it * 8;
        *(float4*)&Qs[d * 128 + lc * 4] =
            *(const float4*)&Qg[(size_t)d * WW + q0 + lc * 4];
    }
    *(float4*)&Ms[tid * 4] = *(const float4*)&mask[(size_t)n * WW + tid * 4];

    ull O2[8][4];                 // (even-k, odd-k) partial sums, per (q,d)
    float m_i[8], l_i[8];
#pragma unroll
    for (int i = 0; i < 8; i++) {
        m_i[i] = -INFINITY; l_i[i] = 0.0f;
#pragma unroll
        for (int j = 0; j < 4; j++) O2[i][j] = 0ull;
    }

    int rq[8];
#pragma unroll
    for (int i = 0; i < 8; i++) rq[i] = (i < 4) ? (4 * ty + i) : (64 + 4 * ty + (i - 4));

    for (int k0 = 0; k0 < WW; k0 += KT) {
        // Load K, V tiles (both channel-major [d][k])
#pragma unroll
        for (int it = 0; it < 8; it++) {
            int d = lr + it * 8;
            *(float4*)&Ks[d * 128 + lc * 4] =
                *(const float4*)&Kg[(size_t)d * WW + k0 + lc * 4];
        }
#pragma unroll
        for (int it = 0; it < 8; it++) {
            int d = lr + it * 8;
            *(float4*)&Vs[d * 132 + lc * 4] =
                *(const float4*)&Vg[(size_t)d * WW + k0 + lc * 4];
        }
        __syncthreads();

        // ---- S = Q^T K (packed along q-pairs) ----
        ull acc2[4][8];
#pragma unroll
        for (int p = 0; p < 4; p++)
#pragma unroll
            for (int j = 0; j < 8; j++) acc2[p][j] = 0ull;

#pragma unroll 4
        for (int d = 0; d < 64; d++) {
            float4 qlo = *(const float4*)&Qs[d * 128 + 4 * ty];
            float4 qhi = *(const float4*)&Qs[d * 128 + 64 + 4 * ty];
            float4 klo = *(const float4*)&Ks[d * 128 + 4 * tx];
            float4 khi = *(const float4*)&Ks[d * 128 + 64 + 4 * tx];
            ull a2[4] = { pk2(qlo.x, qlo.y), pk2(qlo.z, qlo.w),
                          pk2(qhi.x, qhi.y), pk2(qhi.z, qhi.w) };
            float kr[8] = {klo.x, klo.y, klo.z, klo.w, khi.x, khi.y, khi.z, khi.w};
#pragma unroll
            for (int j = 0; j < 8; j++) {
                ull b2 = dup2(kr[j]);
#pragma unroll
                for (int p = 0; p < 4; p++) ffma2(acc2[p][j], a2[p], b2);
            }
        }

        // ---- scale + mask + online softmax (row-pair at a time) ----
        float pcur[8][8];
        float corr[8];
#pragma unroll
        for (int p = 0; p < 4; p++) {
            float sA[8], sB[8];   // rows 2p, 2p+1
#pragma unroll
            for (int j = 0; j < 8; j++) {
                int kc = (j < 4) ? (4 * tx + j) : (64 + 4 * tx + (j - 4));
                float mk = Ms[k0 + kc];
                float2 v = upk2(acc2[p][j]);
                sA[j] = v.x * 0.125f + mk;
                sB[j] = v.y * 0.125f + mk;
            }
#pragma unroll
            for (int half = 0; half < 2; half++) {
                float* s = half ? sB : sA;
                int i = 2 * p + half;
                float mx = s[0];
#pragma unroll
                for (int j = 1; j < 8; j++) mx = fmaxf(mx, s[j]);
#pragma unroll
                for (int off = 8; off >= 1; off >>= 1)
                    mx = fmaxf(mx, __shfl_xor_sync(0xffffffffu, mx, off));
                float nm = fmaxf(m_i[i], mx);
                corr[i] = __expf(m_i[i] - nm);
                m_i[i] = nm;
                float rs = 0.0f;
#pragma unroll
                for (int j = 0; j < 8; j++) {
                    pcur[i][j] = __expf(s[j] - nm);
                    rs += pcur[i][j];
                }
#pragma unroll
                for (int off = 8; off >= 1; off >>= 1)
                    rs += __shfl_xor_sync(0xffffffffu, rs, off);
                l_i[i] = l_i[i] * corr[i] + rs;
            }
        }
        // rescale running output
#pragma unroll
        for (int i = 0; i < 8; i++) {
            ull c2 = dup2(corr[i]);
#pragma unroll
            for (int j = 0; j < 4; j++) fmul2(O2[i][j], c2);
        }

        __syncthreads();   // everyone done reading Ks -> safe to alias as Ps

        // ---- O += P @ V, in two 64-k halves (Ps[128][64] aliases Ks) ----
#pragma unroll
        for (int hf = 0; hf < 2; hf++) {
#pragma unroll
            for (int i = 0; i < 8; i++) {
                float4 pv = { pcur[i][4 * hf + 0], pcur[i][4 * hf + 1],
                              pcur[i][4 * hf + 2], pcur[i][4 * hf + 3] };
                *(float4*)&Ps[rq[i] * 64 + 4 * tx] = pv;
            }
            __syncthreads();

#pragma unroll 2
            for (int k2 = 0; k2 < 32; k2++) {
                ull pa2[8];
#pragma unroll
                for (int i = 0; i < 8; i++)
                    pa2[i] = *(const ull*)&Ps[rq[i] * 64 + 2 * k2];
                ull vb2[4];
#pragma unroll
                for (int j = 0; j < 4; j++)
                    vb2[j] = *(const ull*)&Vs[(4 * tx + j) * 132 + hf * 64 + 2 * k2];
#pragma unroll
                for (int i = 0; i < 8; i++)
#pragma unroll
                    for (int j = 0; j < 4; j++) ffma2(O2[i][j], pa2[i], vb2[j]);
            }
            __syncthreads();
        }
    }

    // ---- finalize: horizontal add of k-pair lanes, normalize, store ----
    float inv[8];
#pragma unroll
    for (int i = 0; i < 8; i++) inv[i] = 1.0f / l_i[i];

#pragma unroll
    for (int j = 0; j < 4; j++) {
        int d = 4 * tx + j;
        float* orow = out + ((size_t)n * CC + h * DD + d) * WW + q0;
        float e[8];
#pragma unroll
        for (int i = 0; i < 8; i++) {
            float2 f2 = upk2(O2[i][j]);
            e[i] = (f2.x + f2.y) * inv[i];
        }
        float4 wlo = {e[0], e[1], e[2], e[3]};
        float4 whi = {e[4], e[5], e[6], e[7]};
        *(float4*)&orow[4 * ty]      = wlo;
        *(float4*)&orow[64 + 4 * ty] = whi;
    }
}

// ---------------------------------------------------------------------------
extern "C" void kernel_launch(void* const* d_in, const int* in_sizes, int n_in,
                              void* d_out, int out_size)
{
    const float* hid  = (const float*)d_in[0];
    const float* mask = (const float*)d_in[1];
    const float* wq   = (const float*)d_in[2];
    const float* bq   = (const float*)d_in[3];
    const float* wk   = (const float*)d_in[4];
    const float* bk   = (const float*)d_in[5];
    const float* wv   = (const float*)d_in[6];
    const float* bv   = (const float*)d_in[7];
    float* out = (float*)d_out;

    dim3 g1(WW / 128, CC / 128, NB * 3);
    qkv_kernel<<<g1, 256>>>(hid, wq, bq, wk, bk, wv, bv);

    const int smem_bytes = SMEM_FLOATS * (int)sizeof(float);
    cudaFuncSetAttribute(attn_kernel,
                         cudaFuncAttributeMaxDynamicSharedMemorySize, smem_bytes);
    dim3 g2(WW / QT, NB * HH);
    attn_kernel<<<g2, 256, smem_bytes>>>(mask, out);
}

// round 8
// speedup vs baseline: 1.4506x; 1.4506x over previous
#include <cuda_runtime.h>
#include <cuda_bf16.h>
#include <math.h>

#define NB 8
#define CC 1024
#define WW 1024
#define HH 16
#define DD 64

typedef unsigned int u32;

// Scratch for Q, K, V projections, each [N, C, W] fp32 (32 MB each).
__device__ float g_q[NB * CC * WW];
__device__ float g_k[NB * CC * WW];
__device__ float g_v[NB * CC * WW];

__device__ __forceinline__ u32 smem_u32(const void* p) {
    u32 a;
    asm("{ .reg .u64 t; cvta.to.shared.u64 t, %1; cvt.u32.u64 %0, t; }"
        : "=r"(a) : "l"(p));
    return a;
}

__device__ __forceinline__ void ldsm_x4(u32& r0, u32& r1, u32& r2, u32& r3, u32 addr) {
    asm volatile("ldmatrix.sync.aligned.m8n8.x4.shared.b16 {%0,%1,%2,%3}, [%4];"
                 : "=r"(r0), "=r"(r1), "=r"(r2), "=r"(r3) : "r"(addr));
}
__device__ __forceinline__ void ldsm_x4_t(u32& r0, u32& r1, u32& r2, u32& r3, u32 addr) {
    asm volatile("ldmatrix.sync.aligned.m8n8.x4.trans.shared.b16 {%0,%1,%2,%3}, [%4];"
                 : "=r"(r0), "=r"(r1), "=r"(r2), "=r"(r3) : "r"(addr));
}
__device__ __forceinline__ void mma16816(float* d, const u32* a, const u32* b) {
    asm volatile(
        "mma.sync.aligned.m16n8k16.row.col.f32.bf16.bf16.f32 "
        "{%0,%1,%2,%3}, {%4,%5,%6,%7}, {%8,%9}, {%0,%1,%2,%3};"
        : "+f"(d[0]), "+f"(d[1]), "+f"(d[2]), "+f"(d[3])
        : "r"(a[0]), "r"(a[1]), "r"(a[2]), "r"(a[3]), "r"(b[0]), "r"(b[1]));
}

__device__ __forceinline__ u32 pack_bf16(float x, float y) {
    __nv_bfloat162 h = __floats2bfloat162_rn(x, y);   // .x = x (low half)
    return *(u32*)&h;
}

// ---------------------------------------------------------------------------
// Kernel 1: QKV projection via mma.sync bf16, 3-term bf16 split (fp32 accuracy).
// Out[o][w] = sum_c W[o][c] * H[c][w] + b[o].   M=o(128), N=w(128), K=c chunks of 32.
// 8 warps as 2(M) x 4(N); warp tile 64x32; register-prefetch double buffering.
// A smem: [128][40] bf16 (hi,lo)   B smem: [32][136] bf16 (hi,lo)
// Row strides 80B / 272B (= 16 * odd) -> conflict-free ldmatrix phases.
// ---------------------------------------------------------------------------
#define APAD 40
#define BPAD 136

__global__ __launch_bounds__(256, 1) void qkv_mma_kernel(
    const float* __restrict__ hid,
    const float* __restrict__ wq, const float* __restrict__ bq,
    const float* __restrict__ wk, const float* __restrict__ bk,
    const float* __restrict__ wv, const float* __restrict__ bv)
{
    __shared__ __nv_bfloat16 Ah[128 * APAD];
    __shared__ __nv_bfloat16 Al[128 * APAD];
    __shared__ __nv_bfloat16 Bh[32 * BPAD];
    __shared__ __nv_bfloat16 Bl[32 * BPAD];

    const int z = blockIdx.z;
    const int n = z / 3;
    const int p = z - 3 * n;

    const float* __restrict__ Wp;
    const float* __restrict__ bias;
    float* __restrict__ out;
    if (p == 0)      { Wp = wq; bias = bq; out = g_q; }
    else if (p == 1) { Wp = wk; bias = bk; out = g_k; }
    else             { Wp = wv; bias = bv; out = g_v; }
    const float* __restrict__ Hs = hid + (size_t)n * CC * WW;
    out += (size_t)n * CC * WW;

    const int o0 = blockIdx.y * 128;     // M
    const int w0 = blockIdx.x * 128;     // N

    const int tid  = threadIdx.x;
    const int wid  = tid >> 5;
    const int lane = tid & 31;
    const int warp_m = wid >> 2;         // 0..1
    const int warp_n = wid & 3;          // 0..3

    // ldmatrix lane decomposition
    const int lr  = lane & 7;
    const int qlo = (lane >> 3) & 1;
    const int qhi = lane >> 4;

    const u32 aHiB = smem_u32(Ah), aLoB = smem_u32(Al);
    const u32 bHiB = smem_u32(Bh), bLoB = smem_u32(Bl);
    // A frag addr: row = warp_m*64 + 16i + lr + 8*qlo ; col = 16*ks + 8*qhi
    const u32 aOff = (u32)((warp_m * 64 + lr + 8 * qlo) * APAD + 8 * qhi) * 2u;
    // B frag addr: row(k) = 16*ks + lr + 8*qlo ; col(n) = warp_n*32 + 16*jp + 8*qhi
    const u32 bOff = (u32)((lr + 8 * qlo) * BPAD + warp_n * 32 + 8 * qhi) * 2u;

    // staging maps
    const int arow = tid >> 1;                 // with i-offset below: 4 f4/thread
    // A: f4id = tid + 256*i -> row = f4id>>3, c4 = f4id&7
    // B: f4id = tid + 256*i -> row = f4id>>5, c4 = f4id&31

    float D[4][4][4];
#pragma unroll
    for (int i = 0; i < 4; i++)
#pragma unroll
        for (int j = 0; j < 4; j++)
#pragma unroll
            for (int r = 0; r < 4; r++) D[i][j][r] = 0.0f;

    float4 aReg[4], bReg[4];

    // initial global fetch (chunk 0)
#pragma unroll
    for (int i = 0; i < 4; i++) {
        const int fa = tid + 256 * i;
        aReg[i] = *(const float4*)&Wp[(size_t)(o0 + (fa >> 3)) * CC + (fa & 7) * 4];
        const int fb = tid + 256 * i;
        bReg[i] = *(const float4*)&Hs[(size_t)(fb >> 5) * WW + w0 + (fb & 31) * 4];
    }

    for (int t = 0; t < 32; t++) {
        // ---- stage current chunk into smem (hi/lo split) ----
#pragma unroll
        for (int i = 0; i < 4; i++) {
            const int fa = tid + 256 * i;
            const int ra = fa >> 3, ca = (fa & 7) * 4;
            float4 v = aReg[i];
            float h0 = __bfloat162float(__float2bfloat16_rn(v.x));
            float h1 = __bfloat162float(__float2bfloat16_rn(v.y));
            float h2 = __bfloat162float(__float2bfloat16_rn(v.z));
            float h3 = __bfloat162float(__float2bfloat16_rn(v.w));
            *(u32*)&Ah[ra * APAD + ca]     = pack_bf16(h0, h1);
            *(u32*)&Ah[ra * APAD + ca + 2] = pack_bf16(h2, h3);
            *(u32*)&Al[ra * APAD + ca]     = pack_bf16(v.x - h0, v.y - h1);
            *(u32*)&Al[ra * APAD + ca + 2] = pack_bf16(v.z - h2, v.w - h3);

            const int fb = tid + 256 * i;
            const int rb = fb >> 5, cb = (fb & 31) * 4;
            float4 u = bReg[i];
            float g0 = __bfloat162float(__float2bfloat16_rn(u.x));
            float g1 = __bfloat162float(__float2bfloat16_rn(u.y));
            float g2 = __bfloat162float(__float2bfloat16_rn(u.z));
            float g3 = __bfloat162float(__float2bfloat16_rn(u.w));
            *(u32*)&Bh[rb * BPAD + cb]     = pack_bf16(g0, g1);
            *(u32*)&Bh[rb * BPAD + cb + 2] = pack_bf16(g2, g3);
            *(u32*)&Bl[rb * BPAD + cb]     = pack_bf16(u.x - g0, u.y - g1);
            *(u32*)&Bl[rb * BPAD + cb + 2] = pack_bf16(u.z - g2, u.w - g3);
        }
        __syncthreads();

        // ---- prefetch next chunk to registers (latency hidden by compute) ----
        if (t < 31) {
            const int kt = (t + 1) * 32;
#pragma unroll
            for (int i = 0; i < 4; i++) {
                const int fa = tid + 256 * i;
                aReg[i] = *(const float4*)&Wp[(size_t)(o0 + (fa >> 3)) * CC + kt + (fa & 7) * 4];
                const int fb = tid + 256 * i;
                bReg[i] = *(const float4*)&Hs[(size_t)(kt + (fb >> 5)) * WW + w0 + (fb & 31) * 4];
            }
        }

        // ---- compute: 2 x k16 steps ----
#pragma unroll
        for (int ks = 0; ks < 2; ks++) {
            u32 ah[4][4], al[4][4], bh[4][2], bl[4][2];
#pragma unroll
            for (int i = 0; i < 4; i++) {
                const u32 off = aOff + (u32)(i * 16 * APAD + ks * 16) * 2u;
                ldsm_x4(ah[i][0], ah[i][1], ah[i][2], ah[i][3], aHiB + off);
                ldsm_x4(al[i][0], al[i][1], al[i][2], al[i][3], aLoB + off);
            }
#pragma unroll
            for (int jp = 0; jp < 2; jp++) {
                const u32 off = bOff + (u32)(ks * 16 * BPAD + jp * 16) * 2u;
                ldsm_x4_t(bh[2 * jp][0], bh[2 * jp][1], bh[2 * jp + 1][0], bh[2 * jp + 1][1],
                          bHiB + off);
                ldsm_x4_t(bl[2 * jp][0], bl[2 * jp][1], bl[2 * jp + 1][0], bl[2 * jp + 1][1],
                          bLoB + off);
            }
#pragma unroll
            for (int i = 0; i < 4; i++)
#pragma unroll
                for (int j = 0; j < 4; j++) {
                    mma16816(D[i][j], ah[i], bh[j]);
                    mma16816(D[i][j], ah[i], bl[j]);
                    mma16816(D[i][j], al[i], bh[j]);
                }
        }
        __syncthreads();
    }

    // ---- epilogue: bias + store ----
    const int g  = lane >> 2;    // row in frag
    const int tg = lane & 3;     // col pair
#pragma unroll
    for (int i = 0; i < 4; i++) {
        const int o_lo = o0 + warp_m * 64 + 16 * i + g;
        const int o_hi = o_lo + 8;
        const float b_lo = bias[o_lo];
        const float b_hi = bias[o_hi];
#pragma unroll
        for (int j = 0; j < 4; j++) {
            const int w = w0 + warp_n * 32 + 8 * j + 2 * tg;
            float2 v0 = { D[i][j][0] + b_lo, D[i][j][1] + b_lo };
            float2 v1 = { D[i][j][2] + b_hi, D[i][j][3] + b_hi };
            *(float2*)&out[(size_t)o_lo * WW + w] = v0;
            *(float2*)&out[(size_t)o_hi * WW + w] = v1;
        }
    }
}

// ---------------------------------------------------------------------------
// Kernel 2: flash attention per (n, h, 64-query tile) — proven 958us version.
// ---------------------------------------------------------------------------
__global__ __launch_bounds__(256) void attn_kernel(
    const float* __restrict__ mask, float* __restrict__ out)
{
    const int qb = blockIdx.x;
    const int nh = blockIdx.y;
    const int n  = nh / HH;
    const int h  = nh - n * HH;
    const int q0 = qb * 64;

    const float* __restrict__ Qg = g_q + ((size_t)n * CC + h * DD) * WW;
    const float* __restrict__ Kg = g_k + ((size_t)n * CC + h * DD) * WW;
    const float* __restrict__ Vg = g_v + ((size_t)n * CC + h * DD) * WW;

    __shared__ float Qs[64][64];
    __shared__ float KP[64][64];
    __shared__ float Vt[64][64];

    const int tid = threadIdx.x;
    const int tx  = tid % 16;
    const int ty  = tid / 16;

    {
        const int c4 = tid % 16;
        const int r  = tid / 16;
#pragma unroll
        for (int it = 0; it < 4; it++) {
            int d = r + it * 16;
            *(float4*)&Qs[d][c4 * 4] =
                *(const float4*)&Qg[(size_t)d * WW + q0 + c4 * 4];
        }
    }

    float m_i[4], l_i[4], O[4][4];
#pragma unroll
    for (int i = 0; i < 4; i++) {
        m_i[i] = -INFINITY; l_i[i] = 0.0f;
#pragma unroll
        for (int j = 0; j < 4; j++) O[i][j] = 0.0f;
    }

    const int vd  = tid % 64;
    const int vk0 = tid / 64;

    for (int k0 = 0; k0 < WW; k0 += 64) {
        {
            const int c4 = tid % 16;
            const int r  = tid / 16;
#pragma unroll
            for (int it = 0; it < 4; it++) {
                int d = r + it * 16;
                *(float4*)&KP[d][c4 * 4] =
                    *(const float4*)&Kg[(size_t)d * WW + k0 + c4 * 4];
            }
        }
#pragma unroll
        for (int it = 0; it < 4; it++) {
            int kk = vk0 + it * 4;
            float4 vv = *(const float4*)&Vg[(size_t)vd * WW + k0 + kk * 4];
            Vt[kk * 4 + 0][vd] = vv.x;
            Vt[kk * 4 + 1][vd] = vv.y;
            Vt[kk * 4 + 2][vd] = vv.z;
            Vt[kk * 4 + 3][vd] = vv.w;
        }
        __syncthreads();

        float s[4][4];
#pragma unroll
        for (int i = 0; i < 4; i++)
#pragma unroll
            for (int j = 0; j < 4; j++) s[i][j] = 0.0f;

#pragma unroll
        for (int d = 0; d < 64; d++) {
            float4 qa = *(const float4*)&Qs[d][ty * 4];
            float4 kb = *(const float4*)&KP[d][tx * 4];
            float qr[4] = {qa.x, qa.y, qa.z, qa.w};
            float kr[4] = {kb.x, kb.y, kb.z, kb.w};
#pragma unroll
            for (int i = 0; i < 4; i++)
#pragma unroll
                for (int j = 0; j < 4; j++) s[i][j] += qr[i] * kr[j];
        }

        float mk[4];
#pragma unroll
        for (int j = 0; j < 4; j++) mk[j] = mask[(size_t)n * WW + k0 + tx * 4 + j];
#pragma unroll
        for (int i = 0; i < 4; i++)
#pragma unroll
            for (int j = 0; j < 4; j++) s[i][j] = s[i][j] * 0.125f + mk[j];

        float pr[4][4];
#pragma unroll
        for (int i = 0; i < 4; i++) {
            float tmax = fmaxf(fmaxf(s[i][0], s[i][1]), fmaxf(s[i][2], s[i][3]));
#pragma unroll
            for (int off = 8; off >= 1; off >>= 1)
                tmax = fmaxf(tmax, __shfl_xor_sync(0xffffffffu, tmax, off));
            float newm = fmaxf(m_i[i], tmax);
            float corr = __expf(m_i[i] - newm);
            float rsum = 0.0f;
#pragma unroll
            for (int j = 0; j < 4; j++) {
                pr[i][j] = __expf(s[i][j] - newm);
                rsum += pr[i][j];
            }
#pragma unroll
            for (int off = 8; off >= 1; off >>= 1)
                rsum += __shfl_xor_sync(0xffffffffu, rsum, off);
            l_i[i] = l_i[i] * corr + rsum;
            m_i[i] = newm;
#pragma unroll
            for (int j = 0; j < 4; j++) O[i][j] *= corr;
        }

        __syncthreads();

#pragma unroll
        for (int i = 0; i < 4; i++) {
            float4 pv = {pr[i][0], pr[i][1], pr[i][2], pr[i][3]};
            *(float4*)&KP[ty * 4 + i][tx * 4] = pv;
        }
        __syncthreads();

#pragma unroll
        for (int k = 0; k < 64; k++) {
            float pa[4];
#pragma unroll
            for (int i = 0; i < 4; i++) pa[i] = KP[ty * 4 + i][k];
            float4 vb = *(const float4*)&Vt[k][tx * 4];
            float vr[4] = {vb.x, vb.y, vb.z, vb.w};
#pragma unroll
            for (int i = 0; i < 4; i++)
#pragma unroll
                for (int j = 0; j < 4; j++) O[i][j] += pa[i] * vr[j];
        }
        __syncthreads();
    }

#pragma unroll
    for (int i = 0; i < 4; i++) {
        float inv = 1.0f / l_i[i];
#pragma unroll
        for (int j = 0; j < 4; j++) O[i][j] *= inv;
    }
#pragma unroll
    for (int j = 0; j < 4; j++) {
        int d = tx * 4 + j;
        float4 o4 = {O[0][j], O[1][j], O[2][j], O[3][j]};
        *(float4*)&out[((size_t)n * CC + h * DD + d) * WW + q0 + ty * 4] = o4;
    }
}

// ---------------------------------------------------------------------------
extern "C" void kernel_launch(void* const* d_in, const int* in_sizes, int n_in,
                              void* d_out, int out_size)
{
    const float* hid  = (const float*)d_in[0];
    const float* mask = (const float*)d_in[1];
    const float* wq   = (const float*)d_in[2];
    const float* bq   = (const float*)d_in[3];
    const float* wk   = (const float*)d_in[4];
    const float* bk   = (const float*)d_in[5];
    const float* wv   = (const float*)d_in[6];
    const float* bv   = (const float*)d_in[7];
    float* out = (float*)d_out;

    dim3 g1(WW / 128, CC / 128, NB * 3);   // (8, 8, 24)
    qkv_mma_kernel<<<g1, 256>>>(hid, wq, bq, wk, bk, wv, bv);

    dim3 g2(WW / 64, NB * HH);             // (16, 128)
    attn_kernel<<<g2, 256>>>(mask, out);
}

// round 9
// speedup vs baseline: 2.4351x; 1.6787x over previous
#include <cuda_runtime.h>
#include <cuda_bf16.h>
#include <math.h>

#define NB 8
#define CC 1024
#define WW 1024
#define HH 16
#define DD 64

typedef unsigned int u32;

// Scratch for Q, K, V projections, each [N, C, W] fp32 (32 MB each).
__device__ float g_q[NB * CC * WW];
__device__ float g_k[NB * CC * WW];
__device__ float g_v[NB * CC * WW];

__device__ __forceinline__ u32 smem_u32(const void* p) {
    u32 a;
    asm("{ .reg .u64 t; cvta.to.shared.u64 t, %1; cvt.u32.u64 %0, t; }"
        : "=r"(a) : "l"(p));
    return a;
}

__device__ __forceinline__ void ldsm_x4(u32& r0, u32& r1, u32& r2, u32& r3, u32 addr) {
    asm volatile("ldmatrix.sync.aligned.m8n8.x4.shared.b16 {%0,%1,%2,%3}, [%4];"
                 : "=r"(r0), "=r"(r1), "=r"(r2), "=r"(r3) : "r"(addr));
}
__device__ __forceinline__ void ldsm_x4_t(u32& r0, u32& r1, u32& r2, u32& r3, u32 addr) {
    asm volatile("ldmatrix.sync.aligned.m8n8.x4.trans.shared.b16 {%0,%1,%2,%3}, [%4];"
                 : "=r"(r0), "=r"(r1), "=r"(r2), "=r"(r3) : "r"(addr));
}
__device__ __forceinline__ void mma16816(float* d, const u32* a, const u32* b) {
    asm volatile(
        "mma.sync.aligned.m16n8k16.row.col.f32.bf16.bf16.f32 "
        "{%0,%1,%2,%3}, {%4,%5,%6,%7}, {%8,%9}, {%0,%1,%2,%3};"
        : "+f"(d[0]), "+f"(d[1]), "+f"(d[2]), "+f"(d[3])
        : "r"(a[0]), "r"(a[1]), "r"(a[2]), "r"(a[3]), "r"(b[0]), "r"(b[1]));
}

__device__ __forceinline__ u32 pack_bf16(float x, float y) {
    __nv_bfloat162 h = __floats2bfloat162_rn(x, y);   // .x = x (low half)
    return *(u32*)&h;
}
__device__ __forceinline__ float bfr(float x) {
    return __bfloat162float(__float2bfloat16_rn(x));
}

// ---------------------------------------------------------------------------
// Kernel 1: QKV projection via mma.sync bf16, 3-term bf16 split (proven R8).
// ---------------------------------------------------------------------------
#define APAD 40
#define BPAD 136

__global__ __launch_bounds__(256, 1) void qkv_mma_kernel(
    const float* __restrict__ hid,
    const float* __restrict__ wq, const float* __restrict__ bq,
    const float* __restrict__ wk, const float* __restrict__ bk,
    const float* __restrict__ wv, const float* __restrict__ bv)
{
    __shared__ __nv_bfloat16 Ah[128 * APAD];
    __shared__ __nv_bfloat16 Al[128 * APAD];
    __shared__ __nv_bfloat16 Bh[32 * BPAD];
    __shared__ __nv_bfloat16 Bl[32 * BPAD];

    const int z = blockIdx.z;
    const int n = z / 3;
    const int p = z - 3 * n;

    const float* __restrict__ Wp;
    const float* __restrict__ bias;
    float* __restrict__ out;
    if (p == 0)      { Wp = wq; bias = bq; out = g_q; }
    else if (p == 1) { Wp = wk; bias = bk; out = g_k; }
    else             { Wp = wv; bias = bv; out = g_v; }
    const float* __restrict__ Hs = hid + (size_t)n * CC * WW;
    out += (size_t)n * CC * WW;

    const int o0 = blockIdx.y * 128;     // M
    const int w0 = blockIdx.x * 128;     // N

    const int tid  = threadIdx.x;
    const int wid  = tid >> 5;
    const int lane = tid & 31;
    const int warp_m = wid >> 2;
    const int warp_n = wid & 3;

    const int lr  = lane & 7;
    const int qlo = (lane >> 3) & 1;
    const int qhi = lane >> 4;

    const u32 aHiB = smem_u32(Ah), aLoB = smem_u32(Al);
    const u32 bHiB = smem_u32(Bh), bLoB = smem_u32(Bl);
    const u32 aOff = (u32)((warp_m * 64 + lr + 8 * qlo) * APAD + 8 * qhi) * 2u;
    const u32 bOff = (u32)((lr + 8 * qlo) * BPAD + warp_n * 32 + 8 * qhi) * 2u;

    float D[4][4][4];
#pragma unroll
    for (int i = 0; i < 4; i++)
#pragma unroll
        for (int j = 0; j < 4; j++)
#pragma unroll
            for (int r = 0; r < 4; r++) D[i][j][r] = 0.0f;

    float4 aReg[4], bReg[4];

#pragma unroll
    for (int i = 0; i < 4; i++) {
        const int fa = tid + 256 * i;
        aReg[i] = *(const float4*)&Wp[(size_t)(o0 + (fa >> 3)) * CC + (fa & 7) * 4];
        const int fb = tid + 256 * i;
        bReg[i] = *(const float4*)&Hs[(size_t)(fb >> 5) * WW + w0 + (fb & 31) * 4];
    }

    for (int t = 0; t < 32; t++) {
#pragma unroll
        for (int i = 0; i < 4; i++) {
            const int fa = tid + 256 * i;
            const int ra = fa >> 3, ca = (fa & 7) * 4;
            float4 v = aReg[i];
            float h0 = bfr(v.x), h1 = bfr(v.y), h2 = bfr(v.z), h3 = bfr(v.w);
            *(u32*)&Ah[ra * APAD + ca]     = pack_bf16(h0, h1);
            *(u32*)&Ah[ra * APAD + ca + 2] = pack_bf16(h2, h3);
            *(u32*)&Al[ra * APAD + ca]     = pack_bf16(v.x - h0, v.y - h1);
            *(u32*)&Al[ra * APAD + ca + 2] = pack_bf16(v.z - h2, v.w - h3);

            const int fb = tid + 256 * i;
            const int rb = fb >> 5, cb = (fb & 31) * 4;
            float4 u = bReg[i];
            float g0 = bfr(u.x), g1 = bfr(u.y), g2 = bfr(u.z), g3 = bfr(u.w);
            *(u32*)&Bh[rb * BPAD + cb]     = pack_bf16(g0, g1);
            *(u32*)&Bh[rb * BPAD + cb + 2] = pack_bf16(g2, g3);
            *(u32*)&Bl[rb * BPAD + cb]     = pack_bf16(u.x - g0, u.y - g1);
            *(u32*)&Bl[rb * BPAD + cb + 2] = pack_bf16(u.z - g2, u.w - g3);
        }
        __syncthreads();

        if (t < 31) {
            const int kt = (t + 1) * 32;
#pragma unroll
            for (int i = 0; i < 4; i++) {
                const int fa = tid + 256 * i;
                aReg[i] = *(const float4*)&Wp[(size_t)(o0 + (fa >> 3)) * CC + kt + (fa & 7) * 4];
                const int fb = tid + 256 * i;
                bReg[i] = *(const float4*)&Hs[(size_t)(kt + (fb >> 5)) * WW + w0 + (fb & 31) * 4];
            }
        }

#pragma unroll
        for (int ks = 0; ks < 2; ks++) {
            u32 ah[4][4], al[4][4], bh[4][2], bl[4][2];
#pragma unroll
            for (int i = 0; i < 4; i++) {
                const u32 off = aOff + (u32)(i * 16 * APAD + ks * 16) * 2u;
                ldsm_x4(ah[i][0], ah[i][1], ah[i][2], ah[i][3], aHiB + off);
                ldsm_x4(al[i][0], al[i][1], al[i][2], al[i][3], aLoB + off);
            }
#pragma unroll
            for (int jp = 0; jp < 2; jp++) {
                const u32 off = bOff + (u32)(ks * 16 * BPAD + jp * 16) * 2u;
                ldsm_x4_t(bh[2 * jp][0], bh[2 * jp][1], bh[2 * jp + 1][0], bh[2 * jp + 1][1],
                          bHiB + off);
                ldsm_x4_t(bl[2 * jp][0], bl[2 * jp][1], bl[2 * jp + 1][0], bl[2 * jp + 1][1],
                          bLoB + off);
            }
#pragma unroll
            for (int i = 0; i < 4; i++)
#pragma unroll
                for (int j = 0; j < 4; j++) {
                    mma16816(D[i][j], ah[i], bh[j]);
                    mma16816(D[i][j], ah[i], bl[j]);
                    mma16816(D[i][j], al[i], bh[j]);
                }
        }
        __syncthreads();
    }

    const int g  = lane >> 2;
    const int tg = lane & 3;
#pragma unroll
    for (int i = 0; i < 4; i++) {
        const int o_lo = o0 + warp_m * 64 + 16 * i + g;
        const int o_hi = o_lo + 8;
        const float b_lo = bias[o_lo];
        const float b_hi = bias[o_hi];
#pragma unroll
        for (int j = 0; j < 4; j++) {
            const int w = w0 + warp_n * 32 + 8 * j + 2 * tg;
            float2 v0 = { D[i][j][0] + b_lo, D[i][j][1] + b_lo };
            float2 v1 = { D[i][j][2] + b_hi, D[i][j][3] + b_hi };
            *(float2*)&out[(size_t)o_lo * WW + w] = v0;
            *(float2*)&out[(size_t)o_hi * WW + w] = v1;
        }
    }
}

// ---------------------------------------------------------------------------
// Kernel 2: flash attention via mma.sync bf16 (FA2 layout), hi/lo splits.
// CTA = 128 queries x full key loop (tiles of 128). 8 warps x 16q each.
// smem (dynamic, 75776 B):
//   KsH [64][136] @0       KsL @17408        (K tile, [d][k], hi/lo)
//   VtH [128][72] @34816   VtL @53248        (V tile transposed [k][d], hi/lo)
//   Ms  [1024]    @71680                     (mask row, fp32)
// Aliases: Qs hi/lo over Vt region (transient, frags hoisted to regs);
//          Obuf fp32 [64][128] over Ks region (epilogue only).
// ---------------------------------------------------------------------------
#define ATTN_SMEM 75776

__global__ __launch_bounds__(256, 1) void attn_mma_kernel(
    const float* __restrict__ mask, float* __restrict__ out)
{
    extern __shared__ char smc[];
    __nv_bfloat16* KsH = (__nv_bfloat16*)(smc);
    __nv_bfloat16* KsL = (__nv_bfloat16*)(smc + 17408);
    __nv_bfloat16* VtH = (__nv_bfloat16*)(smc + 34816);
    __nv_bfloat16* VtL = (__nv_bfloat16*)(smc + 53248);
    float*         Ms  = (float*)(smc + 71680);
    __nv_bfloat16* QsH = VtH;       // alias (transient)
    __nv_bfloat16* QsL = VtL;
    float*         Obuf = (float*)smc;  // alias (epilogue)

    const int qb = blockIdx.x;
    const int nh = blockIdx.y;
    const int n  = nh / HH;
    const int h  = nh - n * HH;
    const int q0 = qb * 128;

    const float* __restrict__ Qg = g_q + ((size_t)n * CC + h * DD) * WW;
    const float* __restrict__ Kg = g_k + ((size_t)n * CC + h * DD) * WW;
    const float* __restrict__ Vg = g_v + ((size_t)n * CC + h * DD) * WW;

    const int tid  = threadIdx.x;
    const int wid  = tid >> 5;
    const int lane = tid & 31;
    const int lr   = lane & 7;
    const int qlo  = (lane >> 3) & 1;
    const int qhi  = lane >> 4;
    const int qw   = wid * 16;

    // stage mask row
    *(float4*)&Ms[tid * 4] = *(const float4*)&mask[(size_t)n * WW + tid * 4];

    // stage Q transposed: Qs[q][d] hi/lo (pack d-pairs)
    {
        const int p = lane;
#pragma unroll
        for (int t = 0; t < 4; t++) {
            const int kc = wid + 8 * t;
            float4 qa = *(const float4*)&Qg[(size_t)(2 * p) * WW + q0 + kc * 4];
            float4 qb4 = *(const float4*)&Qg[(size_t)(2 * p + 1) * WW + q0 + kc * 4];
            float av[4] = {qa.x, qa.y, qa.z, qa.w};
            float bv4[4] = {qb4.x, qb4.y, qb4.z, qb4.w};
#pragma unroll
            for (int e = 0; e < 4; e++) {
                const int q = kc * 4 + e;
                float ah = bfr(av[e]), bh = bfr(bv4[e]);
                *(u32*)&QsH[q * 72 + 2 * p] = pack_bf16(ah, bh);
                *(u32*)&QsL[q * 72 + 2 * p] = pack_bf16(av[e] - ah, bv4[e] - bh);
            }
        }
    }
    __syncthreads();

    // hoist Q A-fragments to registers
    u32 aH[4][4], aL[4][4];
    {
        const u32 baseH = smem_u32(QsH), baseL = smem_u32(QsL);
        const int row = qw + lr + 8 * qlo;
#pragma unroll
        for (int ks = 0; ks < 4; ks++) {
            const u32 off = (u32)(row * 72 + ks * 16 + 8 * qhi) * 2u;
            ldsm_x4(aH[ks][0], aH[ks][1], aH[ks][2], aH[ks][3], baseH + off);
            ldsm_x4(aL[ks][0], aL[ks][1], aL[ks][2], aL[ks][3], baseL + off);
        }
    }
    __syncthreads();   // Q region now reusable as Vt

    float O[8][4];
#pragma unroll
    for (int j = 0; j < 8; j++)
#pragma unroll
        for (int r = 0; r < 4; r++) O[j][r] = 0.0f;
    float mA = -INFINITY, mB = -INFINITY, lA = 0.0f, lB = 0.0f;

    const u32 ksHb = smem_u32(KsH), ksLb = smem_u32(KsL);
    const u32 vtHb = smem_u32(VtH), vtLb = smem_u32(VtL);
    const int krow = lr + 8 * qlo;

    for (int kt = 0; kt < 8; kt++) {
        const int k0 = kt * 128;

        // stage K tile [d][k] hi/lo
#pragma unroll
        for (int t = 0; t < 8; t++) {
            const int idx = tid + 256 * t;
            const int d = idx >> 5, kc = idx & 31;
            float4 v = *(const float4*)&Kg[(size_t)d * WW + k0 + kc * 4];
            float hx = bfr(v.x), hy = bfr(v.y), hz = bfr(v.z), hw = bfr(v.w);
            *(u32*)&KsH[d * 136 + kc * 4]     = pack_bf16(hx, hy);
            *(u32*)&KsH[d * 136 + kc * 4 + 2] = pack_bf16(hz, hw);
            *(u32*)&KsL[d * 136 + kc * 4]     = pack_bf16(v.x - hx, v.y - hy);
            *(u32*)&KsL[d * 136 + kc * 4 + 2] = pack_bf16(v.z - hz, v.w - hw);
        }
        // stage V tile transposed [k][d] hi/lo
        {
            const int p = lane;
#pragma unroll
            for (int t = 0; t < 4; t++) {
                const int kc = wid + 8 * t;
                float4 va = *(const float4*)&Vg[(size_t)(2 * p) * WW + k0 + kc * 4];
                float4 vb = *(const float4*)&Vg[(size_t)(2 * p + 1) * WW + k0 + kc * 4];
                float av[4] = {va.x, va.y, va.z, va.w};
                float bv4[4] = {vb.x, vb.y, vb.z, vb.w};
#pragma unroll
                for (int e = 0; e < 4; e++) {
                    const int k = kc * 4 + e;
                    float ah = bfr(av[e]), bh = bfr(bv4[e]);
                    *(u32*)&VtH[k * 72 + 2 * p] = pack_bf16(ah, bh);
                    *(u32*)&VtL[k * 72 + 2 * p] = pack_bf16(av[e] - ah, bv4[e] - bh);
                }
            }
        }
        __syncthreads();

        // ---- S = Q^T K (3-term split), warp computes 16q x 128k ----
        float sj[16][4];
#pragma unroll
        for (int j = 0; j < 16; j++)
#pragma unroll
            for (int r = 0; r < 4; r++) sj[j][r] = 0.0f;

#pragma unroll
        for (int ks = 0; ks < 4; ks++) {
#pragma unroll
            for (int half = 0; half < 2; half++) {
                u32 bh[8][2], bl[8][2];
#pragma unroll
                for (int jp = 0; jp < 4; jp++) {
                    const int jpg = half * 4 + jp;
                    const u32 off = (u32)((ks * 16 + krow) * 136 + jpg * 16 + 8 * qhi) * 2u;
                    ldsm_x4_t(bh[2 * jp][0], bh[2 * jp][1],
                              bh[2 * jp + 1][0], bh[2 * jp + 1][1], ksHb + off);
                    ldsm_x4_t(bl[2 * jp][0], bl[2 * jp][1],
                              bl[2 * jp + 1][0], bl[2 * jp + 1][1], ksLb + off);
                }
#pragma unroll
                for (int j = 0; j < 8; j++) {
                    const int jj = half * 8 + j;
                    mma16816(sj[jj], aH[ks], bh[j]);
                    mma16816(sj[jj], aH[ks], bl[j]);
                    mma16816(sj[jj], aL[ks], bh[j]);
                }
            }
        }

        // ---- scale + mask + online softmax (rows: A = lane/4, B = +8) ----
#pragma unroll
        for (int j = 0; j < 16; j++) {
            float2 mm = *(const float2*)&Ms[k0 + 8 * j + 2 * (lane & 3)];
            sj[j][0] = sj[j][0] * 0.125f + mm.x;
            sj[j][1] = sj[j][1] * 0.125f + mm.y;
            sj[j][2] = sj[j][2] * 0.125f + mm.x;
            sj[j][3] = sj[j][3] * 0.125f + mm.y;
        }
        float mxA = -INFINITY, mxB = -INFINITY;
#pragma unroll
        for (int j = 0; j < 16; j++) {
            mxA = fmaxf(mxA, fmaxf(sj[j][0], sj[j][1]));
            mxB = fmaxf(mxB, fmaxf(sj[j][2], sj[j][3]));
        }
        mxA = fmaxf(mxA, __shfl_xor_sync(0xffffffffu, mxA, 1));
        mxA = fmaxf(mxA, __shfl_xor_sync(0xffffffffu, mxA, 2));
        mxB = fmaxf(mxB, __shfl_xor_sync(0xffffffffu, mxB, 1));
        mxB = fmaxf(mxB, __shfl_xor_sync(0xffffffffu, mxB, 2));

        const float nmA = fmaxf(mA, mxA), nmB = fmaxf(mB, mxB);
        const float corrA = __expf(mA - nmA), corrB = __expf(mB - nmB);
        mA = nmA; mB = nmB;

        float rsA = 0.0f, rsB = 0.0f;
#pragma unroll
        for (int j = 0; j < 16; j++) {
            sj[j][0] = __expf(sj[j][0] - mA);
            sj[j][1] = __expf(sj[j][1] - mA);
            sj[j][2] = __expf(sj[j][2] - mB);
            sj[j][3] = __expf(sj[j][3] - mB);
            rsA += sj[j][0] + sj[j][1];
            rsB += sj[j][2] + sj[j][3];
        }
        rsA += __shfl_xor_sync(0xffffffffu, rsA, 1);
        rsA += __shfl_xor_sync(0xffffffffu, rsA, 2);
        rsB += __shfl_xor_sync(0xffffffffu, rsB, 1);
        rsB += __shfl_xor_sync(0xffffffffu, rsB, 2);
        lA = lA * corrA + rsA;
        lB = lB * corrB + rsB;

#pragma unroll
        for (int j = 0; j < 8; j++) {
            O[j][0] *= corrA; O[j][1] *= corrA;
            O[j][2] *= corrB; O[j][3] *= corrB;
        }

        // ---- O += P @ V (3-term split), P straight from registers ----
#pragma unroll
        for (int ks2 = 0; ks2 < 8; ks2++) {
            const int j0 = 2 * ks2;
            u32 aPH[4], aPL[4];
            {
                float p0 = sj[j0][0], p1 = sj[j0][1], p2 = sj[j0][2], p3 = sj[j0][3];
                float q0f = sj[j0 + 1][0], q1f = sj[j0 + 1][1],
                      q2f = sj[j0 + 1][2], q3f = sj[j0 + 1][3];
                float h0 = bfr(p0), h1 = bfr(p1), h2 = bfr(p2), h3 = bfr(p3);
                float g0 = bfr(q0f), g1 = bfr(q1f), g2 = bfr(q2f), g3 = bfr(q3f);
                aPH[0] = pack_bf16(h0, h1); aPH[1] = pack_bf16(h2, h3);
                aPH[2] = pack_bf16(g0, g1); aPH[3] = pack_bf16(g2, g3);
                aPL[0] = pack_bf16(p0 - h0, p1 - h1);
                aPL[1] = pack_bf16(p2 - h2, p3 - h3);
                aPL[2] = pack_bf16(q0f - g0, q1f - g1);
                aPL[3] = pack_bf16(q2f - g2, q3f - g3);
            }
#pragma unroll
            for (int half = 0; half < 2; half++) {
                u32 bh[4][2], bl[4][2];
#pragma unroll
                for (int jp = 0; jp < 2; jp++) {
                    const int jpg = half * 2 + jp;
                    const u32 off = (u32)((ks2 * 16 + krow) * 72 + jpg * 16 + 8 * qhi) * 2u;
                    ldsm_x4_t(bh[2 * jp][0], bh[2 * jp][1],
                              bh[2 * jp + 1][0], bh[2 * jp + 1][1], vtHb + off);
                    ldsm_x4_t(bl[2 * jp][0], bl[2 * jp][1],
                              bl[2 * jp + 1][0], bl[2 * jp + 1][1], vtLb + off);
                }
#pragma unroll
                for (int j = 0; j < 4; j++) {
                    const int jj = half * 4 + j;
                    mma16816(O[jj], aPH, bh[j]);
                    mma16816(O[jj], aPH, bl[j]);
                    mma16816(O[jj], aPL, bh[j]);
                }
            }
        }
        __syncthreads();   // before next tile overwrites Ks/Vt
    }

    // ---- finalize: normalize, bounce through smem, coalesced store ----
    const float invA = 1.0f / lA, invB = 1.0f / lB;
#pragma unroll
    for (int j = 0; j < 8; j++) {
        O[j][0] *= invA; O[j][1] *= invA;
        O[j][2] *= invB; O[j][3] *= invB;
    }
    const int r0 = qw + (lane >> 2), r1 = r0 + 8;
#pragma unroll
    for (int j = 0; j < 8; j++) {
        const int d0 = 8 * j + 2 * (lane & 3);
        Obuf[d0 * 128 + r0]       = O[j][0];
        Obuf[(d0 + 1) * 128 + r0] = O[j][1];
        Obuf[d0 * 128 + r1]       = O[j][2];
        Obuf[(d0 + 1) * 128 + r1] = O[j][3];
    }
    __syncthreads();
#pragma unroll
    for (int t = 0; t < 8; t++) {
        const int idx = tid + 256 * t;
        const int r = idx >> 5, c4 = idx & 31;
        *(float4*)&out[((size_t)n * CC + h * DD + r) * WW + q0 + c4 * 4] =
            *(float4*)&Obuf[r * 128 + c4 * 4];
    }
}

// ---------------------------------------------------------------------------
extern "C" void kernel_launch(void* const* d_in, const int* in_sizes, int n_in,
                              void* d_out, int out_size)
{
    const float* hid  = (const float*)d_in[0];
    const float* mask = (const float*)d_in[1];
    const float* wq   = (const float*)d_in[2];
    const float* bq   = (const float*)d_in[3];
    const float* wk   = (const float*)d_in[4];
    const float* bk   = (const float*)d_in[5];
    const float* wv   = (const float*)d_in[6];
    const float* bv   = (const float*)d_in[7];
    float* out = (float*)d_out;

    dim3 g1(WW / 128, CC / 128, NB * 3);   // (8, 8, 24)
    qkv_mma_kernel<<<g1, 256>>>(hid, wq, bq, wk, bk, wv, bv);

    cudaFuncSetAttribute(attn_mma_kernel,
                         cudaFuncAttributeMaxDynamicSharedMemorySize, ATTN_SMEM);
    dim3 g2(WW / 128, NB * HH);            // (8, 128)
    attn_mma_kernel<<<g2, 256, ATTN_SMEM>>>(mask, out);
}

// round 10
// speedup vs baseline: 2.7326x; 1.1222x over previous
#include <cuda_runtime.h>
#include <cuda_bf16.h>
#include <math.h>

#define NB 8
#define CC 1024
#define WW 1024
#define HH 16
#define DD 64

typedef unsigned int u32;

// Scratch: Q,K,V projections as bf16 hi/lo pairs, [n][c][w] (16 MB each).
__device__ __nv_bfloat16 g_qh[NB * CC * WW];
__device__ __nv_bfloat16 g_ql[NB * CC * WW];
__device__ __nv_bfloat16 g_kh[NB * CC * WW];
__device__ __nv_bfloat16 g_kl[NB * CC * WW];
__device__ __nv_bfloat16 g_vh[NB * CC * WW];
__device__ __nv_bfloat16 g_vl[NB * CC * WW];

__device__ __forceinline__ u32 smem_u32(const void* p) {
    u32 a;
    asm("{ .reg .u64 t; cvta.to.shared.u64 t, %1; cvt.u32.u64 %0, t; }"
        : "=r"(a) : "l"(p));
    return a;
}

__device__ __forceinline__ void ldsm_x4(u32& r0, u32& r1, u32& r2, u32& r3, u32 addr) {
    asm volatile("ldmatrix.sync.aligned.m8n8.x4.shared.b16 {%0,%1,%2,%3}, [%4];"
                 : "=r"(r0), "=r"(r1), "=r"(r2), "=r"(r3) : "r"(addr));
}
__device__ __forceinline__ void ldsm_x4_t(u32& r0, u32& r1, u32& r2, u32& r3, u32 addr) {
    asm volatile("ldmatrix.sync.aligned.m8n8.x4.trans.shared.b16 {%0,%1,%2,%3}, [%4];"
                 : "=r"(r0), "=r"(r1), "=r"(r2), "=r"(r3) : "r"(addr));
}
__device__ __forceinline__ void mma16816(float* d, const u32* a, const u32* b) {
    asm volatile(
        "mma.sync.aligned.m16n8k16.row.col.f32.bf16.bf16.f32 "
        "{%0,%1,%2,%3}, {%4,%5,%6,%7}, {%8,%9}, {%0,%1,%2,%3};"
        : "+f"(d[0]), "+f"(d[1]), "+f"(d[2]), "+f"(d[3])
        : "r"(a[0]), "r"(a[1]), "r"(a[2]), "r"(a[3]), "r"(b[0]), "r"(b[1]));
}
__device__ __forceinline__ void cp16(u32 dst, const void* src) {
    asm volatile("cp.async.cg.shared.global [%0], [%1], 16;" :: "r"(dst), "l"(src));
}
#define CP_COMMIT() asm volatile("cp.async.commit_group;")
#define CP_WAIT0()  asm volatile("cp.async.wait_group 0;")
#define CP_WAIT1()  asm volatile("cp.async.wait_group 1;")

__device__ __forceinline__ u32 pack_bf16(float x, float y) {
    __nv_bfloat162 h = __floats2bfloat162_rn(x, y);   // .x = x (low half)
    return *(u32*)&h;
}
__device__ __forceinline__ float bfr(float x) {
    return __bfloat162float(__float2bfloat16_rn(x));
}

// ---------------------------------------------------------------------------
// Kernel 1: QKV projection via mma.sync bf16, 3-term split (R8 mainloop).
// Epilogue writes bf16 hi/lo scratch (packed u32 stores, coalesced).
// ---------------------------------------------------------------------------
#define APAD 40
#define BPAD 136

__global__ __launch_bounds__(256, 1) void qkv_mma_kernel(
    const float* __restrict__ hid,
    const float* __restrict__ wq, const float* __restrict__ bq,
    const float* __restrict__ wk, const float* __restrict__ bk,
    const float* __restrict__ wv, const float* __restrict__ bv)
{
    __shared__ __nv_bfloat16 Ah[128 * APAD];
    __shared__ __nv_bfloat16 Al[128 * APAD];
    __shared__ __nv_bfloat16 Bh[32 * BPAD];
    __shared__ __nv_bfloat16 Bl[32 * BPAD];

    const int z = blockIdx.z;
    const int n = z / 3;
    const int p = z - 3 * n;

    const float* __restrict__ Wp;
    const float* __restrict__ bias;
    __nv_bfloat16 *gh, *gl;
    if (p == 0)      { Wp = wq; bias = bq; gh = g_qh; gl = g_ql; }
    else if (p == 1) { Wp = wk; bias = bk; gh = g_kh; gl = g_kl; }
    else             { Wp = wv; bias = bv; gh = g_vh; gl = g_vl; }
    const float* __restrict__ Hs = hid + (size_t)n * CC * WW;
    gh += (size_t)n * CC * WW;
    gl += (size_t)n * CC * WW;

    const int o0 = blockIdx.y * 128;     // M
    const int w0 = blockIdx.x * 128;     // N

    const int tid  = threadIdx.x;
    const int wid  = tid >> 5;
    const int lane = tid & 31;
    const int warp_m = wid >> 2;
    const int warp_n = wid & 3;

    const int lr  = lane & 7;
    const int qlo = (lane >> 3) & 1;
    const int qhi = lane >> 4;

    const u32 aHiB = smem_u32(Ah), aLoB = smem_u32(Al);
    const u32 bHiB = smem_u32(Bh), bLoB = smem_u32(Bl);
    const u32 aOff = (u32)((warp_m * 64 + lr + 8 * qlo) * APAD + 8 * qhi) * 2u;
    const u32 bOff = (u32)((lr + 8 * qlo) * BPAD + warp_n * 32 + 8 * qhi) * 2u;

    float D[4][4][4];
#pragma unroll
    for (int i = 0; i < 4; i++)
#pragma unroll
        for (int j = 0; j < 4; j++)
#pragma unroll
            for (int r = 0; r < 4; r++) D[i][j][r] = 0.0f;

    float4 aReg[4], bReg[4];

#pragma unroll
    for (int i = 0; i < 4; i++) {
        const int fa = tid + 256 * i;
        aReg[i] = *(const float4*)&Wp[(size_t)(o0 + (fa >> 3)) * CC + (fa & 7) * 4];
        const int fb = tid + 256 * i;
        bReg[i] = *(const float4*)&Hs[(size_t)(fb >> 5) * WW + w0 + (fb & 31) * 4];
    }

    for (int t = 0; t < 32; t++) {
#pragma unroll
        for (int i = 0; i < 4; i++) {
            const int fa = tid + 256 * i;
            const int ra = fa >> 3, ca = (fa & 7) * 4;
            float4 v = aReg[i];
            float h0 = bfr(v.x), h1 = bfr(v.y), h2 = bfr(v.z), h3 = bfr(v.w);
            *(u32*)&Ah[ra * APAD + ca]     = pack_bf16(h0, h1);
            *(u32*)&Ah[ra * APAD + ca + 2] = pack_bf16(h2, h3);
            *(u32*)&Al[ra * APAD + ca]     = pack_bf16(v.x - h0, v.y - h1);
            *(u32*)&Al[ra * APAD + ca + 2] = pack_bf16(v.z - h2, v.w - h3);

            const int fb = tid + 256 * i;
            const int rb = fb >> 5, cb = (fb & 31) * 4;
            float4 u = bReg[i];
            float g0 = bfr(u.x), g1 = bfr(u.y), g2 = bfr(u.z), g3 = bfr(u.w);
            *(u32*)&Bh[rb * BPAD + cb]     = pack_bf16(g0, g1);
            *(u32*)&Bh[rb * BPAD + cb + 2] = pack_bf16(g2, g3);
            *(u32*)&Bl[rb * BPAD + cb]     = pack_bf16(u.x - g0, u.y - g1);
            *(u32*)&Bl[rb * BPAD + cb + 2] = pack_bf16(u.z - g2, u.w - g3);
        }
        __syncthreads();

        if (t < 31) {
            const int kt = (t + 1) * 32;
#pragma unroll
            for (int i = 0; i < 4; i++) {
                const int fa = tid + 256 * i;
                aReg[i] = *(const float4*)&Wp[(size_t)(o0 + (fa >> 3)) * CC + kt + (fa & 7) * 4];
                const int fb = tid + 256 * i;
                bReg[i] = *(const float4*)&Hs[(size_t)(kt + (fb >> 5)) * WW + w0 + (fb & 31) * 4];
            }
        }

#pragma unroll
        for (int ks = 0; ks < 2; ks++) {
            u32 ah[4][4], al[4][4], bh[4][2], bl[4][2];
#pragma unroll
            for (int i = 0; i < 4; i++) {
                const u32 off = aOff + (u32)(i * 16 * APAD + ks * 16) * 2u;
                ldsm_x4(ah[i][0], ah[i][1], ah[i][2], ah[i][3], aHiB + off);
                ldsm_x4(al[i][0], al[i][1], al[i][2], al[i][3], aLoB + off);
            }
#pragma unroll
            for (int jp = 0; jp < 2; jp++) {
                const u32 off = bOff + (u32)(ks * 16 * BPAD + jp * 16) * 2u;
                ldsm_x4_t(bh[2 * jp][0], bh[2 * jp][1], bh[2 * jp + 1][0], bh[2 * jp + 1][1],
                          bHiB + off);
                ldsm_x4_t(bl[2 * jp][0], bl[2 * jp][1], bl[2 * jp + 1][0], bl[2 * jp + 1][1],
                          bLoB + off);
            }
#pragma unroll
            for (int i = 0; i < 4; i++)
#pragma unroll
                for (int j = 0; j < 4; j++) {
                    mma16816(D[i][j], ah[i], bh[j]);
                    mma16816(D[i][j], ah[i], bl[j]);
                    mma16816(D[i][j], al[i], bh[j]);
                }
        }
        __syncthreads();
    }

    // epilogue: bias + hi/lo split + packed u32 stores
    const int g  = lane >> 2;
    const int tg = lane & 3;
#pragma unroll
    for (int i = 0; i < 4; i++) {
        const int o_lo = o0 + warp_m * 64 + 16 * i + g;
        const int o_hi = o_lo + 8;
        const float b_lo = bias[o_lo];
        const float b_hi = bias[o_hi];
#pragma unroll
        for (int j = 0; j < 4; j++) {
            const int w = w0 + warp_n * 32 + 8 * j + 2 * tg;
            float v0 = D[i][j][0] + b_lo, v1 = D[i][j][1] + b_lo;
            float v2 = D[i][j][2] + b_hi, v3 = D[i][j][3] + b_hi;
            float h0 = bfr(v0), h1 = bfr(v1), h2 = bfr(v2), h3 = bfr(v3);
            *(u32*)&gh[(size_t)o_lo * WW + w] = pack_bf16(h0, h1);
            *(u32*)&gl[(size_t)o_lo * WW + w] = pack_bf16(v0 - h0, v1 - h1);
            *(u32*)&gh[(size_t)o_hi * WW + w] = pack_bf16(h2, h3);
            *(u32*)&gl[(size_t)o_hi * WW + w] = pack_bf16(v2 - h2, v3 - h3);
        }
    }
}

// ---------------------------------------------------------------------------
// Kernel 2: flash attention, mma.sync bf16, pre-split scratch, cp.async
// pipeline, 2 CTAs/SM.  CTA = 128q; key tiles of 64, double-buffered.
// smem layout (bytes, dynamic 112640):
//   QH [64][136]   @0       QL @17408        (Q [d][q], persistent)
//   KH/KL buf b    @34816 + b*18432 (+9216)  ([d][k], 64x72 el, stride 144B)
//   VH/VL buf b    @71680 + b*18432 (+9216)
//   Ms (1024 fp32) @108544
//   Obuf fp32 [64][128] aliases Q region at end.
// Fragments: Q a-frag = trans-ldsm on [d][q]; K b-frag = trans-ldsm on [d][k];
//            V b-frag = non-trans ldsm on [d][k] (col-major B = [n][k]).
// ---------------------------------------------------------------------------
#define ATTN_SMEM 112640

__global__ __launch_bounds__(256, 2) void attn_mma_kernel(
    const float* __restrict__ mask, float* __restrict__ out)
{
    extern __shared__ char smc[];
    const u32 sb = smem_u32(smc);

    const int qb = blockIdx.x;
    const int nh = blockIdx.y;
    const int n  = nh >> 4;
    const int h  = nh & 15;
    const int q0 = qb * 128;

    const size_t cbase = ((size_t)n * CC + h * DD) * WW;
    const __nv_bfloat16* __restrict__ Qh = g_qh + cbase;
    const __nv_bfloat16* __restrict__ Ql = g_ql + cbase;
    const __nv_bfloat16* __restrict__ Kh = g_kh + cbase;
    const __nv_bfloat16* __restrict__ Kl = g_kl + cbase;
    const __nv_bfloat16* __restrict__ Vh = g_vh + cbase;
    const __nv_bfloat16* __restrict__ Vl = g_vl + cbase;

    const int tid  = threadIdx.x;
    const int wid  = tid >> 5;
    const int lane = tid & 31;
    const int qw   = wid * 16;
    const int r    = lane & 7;
    const int b3   = (lane >> 3) & 1;
    const int b4   = lane >> 4;
    const int gr   = lane >> 2;
    const int tg   = lane & 3;

    // per-lane ldmatrix base offsets
    const u32 qa_off = (u32)((8 * b4 + r) * 272 + (qw + 8 * b3) * 2);  // Q trans
    const u32 ka_off = (u32)((8 * b3 + r) * 144 + (8 * b4) * 2);       // K trans
    const u32 va_off = (u32)((8 * b4 + r) * 144 + (8 * b3) * 2);       // V non-trans

    float* MsP = (float*)(smc + 108544);

    // ---- prologue: Q + mask + tile0 via cp.async ----
#pragma unroll
    for (int i = 0; i < 4; i++) {
        const int idx = tid + 256 * i;
        const int row = idx >> 4, c = idx & 15;
        cp16(sb + row * 272 + c * 16,         Qh + (size_t)row * WW + q0 + c * 8);
        cp16(sb + 17408 + row * 272 + c * 16, Ql + (size_t)row * WW + q0 + c * 8);
    }
    cp16(sb + 108544 + tid * 16, mask + (size_t)n * WW + tid * 4);
#pragma unroll
    for (int i = 0; i < 2; i++) {
        const int idx = tid + 256 * i;
        const int row = idx >> 3, c = idx & 7;
        const size_t so = (size_t)row * WW + c * 8;
        const u32 d = row * 144 + c * 16;
        cp16(sb + 34816 + d, Kh + so);
        cp16(sb + 44032 + d, Kl + so);
        cp16(sb + 71680 + d, Vh + so);
        cp16(sb + 80896 + d, Vl + so);
    }
    CP_COMMIT();

    float sj[8][4], O[8][4];
    float mA = -INFINITY, mB = -INFINITY, lA = 0.0f, lB = 0.0f;
#pragma unroll
    for (int j = 0; j < 8; j++)
#pragma unroll
        for (int q = 0; q < 4; q++) O[j][q] = 0.0f;

    for (int t = 0; t < 16; t++) {
        const int b = t & 1;
        const u32 khb = sb + 34816 + b * 18432;
        const u32 vhb = sb + 71680 + b * 18432;

        if (t + 1 < 16) {
            const int nb = (t + 1) & 1;
            const int k0n = (t + 1) * 64;
#pragma unroll
            for (int i = 0; i < 2; i++) {
                const int idx = tid + 256 * i;
                const int row = idx >> 3, c = idx & 7;
                const size_t so = (size_t)row * WW + k0n + c * 8;
                const u32 d = row * 144 + c * 16;
                cp16(sb + 34816 + nb * 18432 + d, Kh + so);
                cp16(sb + 44032 + nb * 18432 + d, Kl + so);
                cp16(sb + 71680 + nb * 18432 + d, Vh + so);
                cp16(sb + 80896 + nb * 18432 + d, Vl + so);
            }
            CP_COMMIT();
            CP_WAIT1();
        } else {
            CP_WAIT0();
        }
        __syncthreads();

        // ---- S = Q^T K (3-term), 16q x 64k per warp ----
#pragma unroll
        for (int j = 0; j < 8; j++)
#pragma unroll
            for (int q = 0; q < 4; q++) sj[j][q] = 0.0f;

#pragma unroll
        for (int ks = 0; ks < 4; ks++) {
            u32 aH[4], aL[4];
            const u32 qa = sb + ks * 16 * 272 + qa_off;
            ldsm_x4_t(aH[0], aH[1], aH[2], aH[3], qa);
            ldsm_x4_t(aL[0], aL[1], aL[2], aL[3], qa + 17408);
#pragma unroll
            for (int jpg = 0; jpg < 4; jpg++) {
                u32 bh[4], bl[4];
                const u32 ka = khb + ks * 16 * 144 + jpg * 32 + ka_off;
                ldsm_x4_t(bh[0], bh[1], bh[2], bh[3], ka);
                ldsm_x4_t(bl[0], bl[1], bl[2], bl[3], ka + 9216);
                const int jj = 2 * jpg;
                mma16816(sj[jj],     aH, bh);
                mma16816(sj[jj],     aH, bl);
                mma16816(sj[jj],     aL, bh);
                mma16816(sj[jj + 1], aH, bh + 2);
                mma16816(sj[jj + 1], aH, bl + 2);
                mma16816(sj[jj + 1], aL, bh + 2);
            }
        }

        // ---- scale + mask + online softmax ----
        const int k0 = t * 64;
#pragma unroll
        for (int j = 0; j < 8; j++) {
            float2 mm = *(float2*)&MsP[k0 + 8 * j + 2 * tg];
            sj[j][0] = sj[j][0] * 0.125f + mm.x;
            sj[j][1] = sj[j][1] * 0.125f + mm.y;
            sj[j][2] = sj[j][2] * 0.125f + mm.x;
            sj[j][3] = sj[j][3] * 0.125f + mm.y;
        }
        float mxA = -INFINITY, mxB = -INFINITY;
#pragma unroll
        for (int j = 0; j < 8; j++) {
            mxA = fmaxf(mxA, fmaxf(sj[j][0], sj[j][1]));
            mxB = fmaxf(mxB, fmaxf(sj[j][2], sj[j][3]));
        }
        mxA = fmaxf(mxA, __shfl_xor_sync(0xffffffffu, mxA, 1));
        mxA = fmaxf(mxA, __shfl_xor_sync(0xffffffffu, mxA, 2));
        mxB = fmaxf(mxB, __shfl_xor_sync(0xffffffffu, mxB, 1));
        mxB = fmaxf(mxB, __shfl_xor_sync(0xffffffffu, mxB, 2));

        const float nmA = fmaxf(mA, mxA), nmB = fmaxf(mB, mxB);
        const float corrA = __expf(mA - nmA), corrB = __expf(mB - nmB);
        mA = nmA; mB = nmB;

        float rsA = 0.0f, rsB = 0.0f;
#pragma unroll
        for (int j = 0; j < 8; j++) {
            sj[j][0] = __expf(sj[j][0] - mA);
            sj[j][1] = __expf(sj[j][1] - mA);
            sj[j][2] = __expf(sj[j][2] - mB);
            sj[j][3] = __expf(sj[j][3] - mB);
            rsA += sj[j][0] + sj[j][1];
            rsB += sj[j][2] + sj[j][3];
        }
        rsA += __shfl_xor_sync(0xffffffffu, rsA, 1);
        rsA += __shfl_xor_sync(0xffffffffu, rsA, 2);
        rsB += __shfl_xor_sync(0xffffffffu, rsB, 1);
        rsB += __shfl_xor_sync(0xffffffffu, rsB, 2);
        lA = lA * corrA + rsA;
        lB = lB * corrB + rsB;

#pragma unroll
        for (int j = 0; j < 8; j++) {
            O[j][0] *= corrA; O[j][1] *= corrA;
            O[j][2] *= corrB; O[j][3] *= corrB;
        }

        // ---- O += P @ V (3-term), P from registers ----
#pragma unroll
        for (int ks2 = 0; ks2 < 4; ks2++) {
            const int j0 = 2 * ks2;
            u32 aPH[4], aPL[4];
            {
                float p0 = sj[j0][0], p1 = sj[j0][1], p2 = sj[j0][2], p3 = sj[j0][3];
                float u0 = sj[j0 + 1][0], u1 = sj[j0 + 1][1];
                float u2 = sj[j0 + 1][2], u3 = sj[j0 + 1][3];
                float h0 = bfr(p0), h1 = bfr(p1), h2 = bfr(p2), h3 = bfr(p3);
                float g0 = bfr(u0), g1 = bfr(u1), g2 = bfr(u2), g3 = bfr(u3);
                aPH[0] = pack_bf16(h0, h1); aPH[1] = pack_bf16(h2, h3);
                aPH[2] = pack_bf16(g0, g1); aPH[3] = pack_bf16(g2, g3);
                aPL[0] = pack_bf16(p0 - h0, p1 - h1);
                aPL[1] = pack_bf16(p2 - h2, p3 - h3);
                aPL[2] = pack_bf16(u0 - g0, u1 - g1);
                aPL[3] = pack_bf16(u2 - g2, u3 - g3);
            }
#pragma unroll
            for (int jpg = 0; jpg < 4; jpg++) {
                u32 bh[4], bl[4];
                const u32 va = vhb + jpg * 16 * 144 + ks2 * 32 + va_off;
                ldsm_x4(bh[0], bh[1], bh[2], bh[3], va);
                ldsm_x4(bl[0], bl[1], bl[2], bl[3], va + 9216);
                const int jj = 2 * jpg;
                mma16816(O[jj],     aPH, bh);
                mma16816(O[jj],     aPH, bl);
                mma16816(O[jj],     aPL, bh);
                mma16816(O[jj + 1], aPH, bh + 2);
                mma16816(O[jj + 1], aPH, bl + 2);
                mma16816(O[jj + 1], aPL, bh + 2);
            }
        }
        __syncthreads();
    }

    // ---- finalize: normalize, bounce via smem (aliases Q), coalesced out ----
    const float invA = 1.0f / lA, invB = 1.0f / lB;
#pragma unroll
    for (int j = 0; j < 8; j++) {
        O[j][0] *= invA; O[j][1] *= invA;
        O[j][2] *= invB; O[j][3] *= invB;
    }
    float* Obuf = (float*)smc;
    const int r0 = qw + gr, r1 = r0 + 8;
#pragma unroll
    for (int j = 0; j < 8; j++) {
        const int d0 = 8 * j + 2 * tg;
        Obuf[d0 * 128 + r0]       = O[j][0];
        Obuf[(d0 + 1) * 128 + r0] = O[j][1];
        Obuf[d0 * 128 + r1]       = O[j][2];
        Obuf[(d0 + 1) * 128 + r1] = O[j][3];
    }
    __syncthreads();
#pragma unroll
    for (int i = 0; i < 8; i++) {
        const int idx = tid + 256 * i;
        const int row = idx >> 5, c4 = idx & 31;
        *(float4*)&out[((size_t)n * CC + h * DD + row) * WW + q0 + c4 * 4] =
            *(float4*)&Obuf[row * 128 + c4 * 4];
    }
}

// ---------------------------------------------------------------------------
extern "C" void kernel_launch(void* const* d_in, const int* in_sizes, int n_in,
                              void* d_out, int out_size)
{
    const float* hid  = (const float*)d_in[0];
    const float* mask = (const float*)d_in[1];
    const float* wq   = (const float*)d_in[2];
    const float* bq   = (const float*)d_in[3];
    const float* wk   = (const float*)d_in[4];
    const float* bk   = (const float*)d_in[5];
    const float* wv   = (const float*)d_in[6];
    const float* bv   = (const float*)d_in[7];
    float* out = (float*)d_out;

    dim3 g1(WW / 128, CC / 128, NB * 3);   // (8, 8, 24)
    qkv_mma_kernel<<<g1, 256>>>(hid, wq, bq, wk, bk, wv, bv);

    cudaFuncSetAttribute(attn_mma_kernel,
                         cudaFuncAttributeMaxDynamicSharedMemorySize, ATTN_SMEM);
    dim3 g2(WW / 128, NB * HH);            // (8, 128)
    attn_mma_kernel<<<g2, 256, ATTN_SMEM>>>(mask, out);
}

// round 14
// speedup vs baseline: 3.0077x; 1.1006x over previous
#include <cuda_runtime.h>
#include <cuda_bf16.h>
#include <math.h>

#define NB 8
#define CC 1024
#define WW 1024
#define HH 16
#define DD 64

typedef unsigned int u32;

// Scratch: Q,K,V projections as bf16 hi/lo pairs, [n][c][w] (16 MB each).
__device__ __nv_bfloat16 g_qh[NB * CC * WW];
__device__ __nv_bfloat16 g_ql[NB * CC * WW];
__device__ __nv_bfloat16 g_kh[NB * CC * WW];
__device__ __nv_bfloat16 g_kl[NB * CC * WW];
__device__ __nv_bfloat16 g_vh[NB * CC * WW];
__device__ __nv_bfloat16 g_vl[NB * CC * WW];
// Pre-split inputs: hidden states [n][c][w], weights [p][o][c].
__device__ __nv_bfloat16 g_hh[NB * CC * WW];
__device__ __nv_bfloat16 g_hl[NB * CC * WW];
__device__ __nv_bfloat16 g_wh[3 * CC * CC];
__device__ __nv_bfloat16 g_wl[3 * CC * CC];

__device__ __forceinline__ u32 smem_u32(const void* p) {
    u32 a;
    asm("{ .reg .u64 t; cvta.to.shared.u64 t, %1; cvt.u32.u64 %0, t; }"
        : "=r"(a) : "l"(p));
    return a;
}
__device__ __forceinline__ void ldsm_x4(u32& r0, u32& r1, u32& r2, u32& r3, u32 addr) {
    asm volatile("ldmatrix.sync.aligned.m8n8.x4.shared.b16 {%0,%1,%2,%3}, [%4];"
                 : "=r"(r0), "=r"(r1), "=r"(r2), "=r"(r3) : "r"(addr));
}
__device__ __forceinline__ void ldsm_x4_t(u32& r0, u32& r1, u32& r2, u32& r3, u32 addr) {
    asm volatile("ldmatrix.sync.aligned.m8n8.x4.trans.shared.b16 {%0,%1,%2,%3}, [%4];"
                 : "=r"(r0), "=r"(r1), "=r"(r2), "=r"(r3) : "r"(addr));
}
__device__ __forceinline__ void mma16816(float* d, const u32* a, const u32* b) {
    asm volatile(
        "mma.sync.aligned.m16n8k16.row.col.f32.bf16.bf16.f32 "
        "{%0,%1,%2,%3}, {%4,%5,%6,%7}, {%8,%9}, {%0,%1,%2,%3};"
        : "+f"(d[0]), "+f"(d[1]), "+f"(d[2]), "+f"(d[3])
        : "r"(a[0]), "r"(a[1]), "r"(a[2]), "r"(a[3]), "r"(b[0]), "r"(b[1]));
}
__device__ __forceinline__ void cp16(u32 dst, const void* src) {
    asm volatile("cp.async.cg.shared.global [%0], [%1], 16;" :: "r"(dst), "l"(src));
}
#define CP_COMMIT() asm volatile("cp.async.commit_group;")
#define CP_WAIT0()  asm volatile("cp.async.wait_group 0;")
#define CP_WAIT1()  asm volatile("cp.async.wait_group 1;")

__device__ __forceinline__ u32 pack_bf16(float x, float y) {
    __nv_bfloat162 h = __floats2bfloat162_rn(x, y);   // .x = x (low half)
    return *(u32*)&h;
}
__device__ __forceinline__ float bfr(float x) {
    return __bfloat162float(__float2bfloat16_rn(x));
}

// ---------------------------------------------------------------------------
// Kernel 0: elementwise hi/lo bf16 split of hidden states + weights.
// Blocks 0..8191 -> hid, 8192..9215 -> wq, 9216..10239 -> wk, 10240..11263 -> wv
// Each block: 256 threads x 1 float4.
// ---------------------------------------------------------------------------
__global__ __launch_bounds__(256) void split_kernel(
    const float* __restrict__ hid,
    const float* __restrict__ wq, const float* __restrict__ wk,
    const float* __restrict__ wv)
{
    const int b = blockIdx.x;
    const float* __restrict__ src;
    __nv_bfloat16 *dh, *dl;
    size_t f4base;
    if (b < 8192)       { src = hid; dh = g_hh; dl = g_hl; f4base = (size_t)b * 256; }
    else if (b < 9216)  { src = wq; dh = g_wh; dl = g_wl; f4base = (size_t)(b - 8192) * 256; }
    else if (b < 10240) { src = wk; dh = g_wh + (size_t)CC * CC; dl = g_wl + (size_t)CC * CC;
                          f4base = (size_t)(b - 9216) * 256; }
    else                { src = wv; dh = g_wh + 2 * (size_t)CC * CC; dl = g_wl + 2 * (size_t)CC * CC;
                          f4base = (size_t)(b - 10240) * 256; }
    const size_t e = (f4base + threadIdx.x) * 4;
    float4 v = *(const float4*)&src[e];
    float h0 = bfr(v.x), h1 = bfr(v.y), h2 = bfr(v.z), h3 = bfr(v.w);
    *(u32*)&dh[e]     = pack_bf16(h0, h1);
    *(u32*)&dh[e + 2] = pack_bf16(h2, h3);
    *(u32*)&dl[e]     = pack_bf16(v.x - h0, v.y - h1);
    *(u32*)&dl[e + 2] = pack_bf16(v.z - h2, v.w - h3);
}

// ---------------------------------------------------------------------------
// Kernel 1: QKV projection, mma.sync bf16 3-term, pre-split inputs,
// cp.async double-buffered pipeline, 2 CTAs/SM.
// Out[o][w] = sum_c W[o][c]*H[c][w] + b[o];  CTA = 128o x 128w, k chunks of 32.
// smem per buffer (37888 B): AH[128][40] @0, AL @10240, BH[32][136] @20480,
//                            BL @29184.  Two buffers = 75776 B dynamic.
// ---------------------------------------------------------------------------
#define QKV_SMEM 75776

__global__ __launch_bounds__(256, 2) void qkv_mma_kernel(
    const float* __restrict__ bq, const float* __restrict__ bk,
    const float* __restrict__ bv)
{
    extern __shared__ char smc[];
    const u32 sb = smem_u32(smc);

    const int z = blockIdx.z;
    const int n = z / 3;
    const int p = z - 3 * n;

    const float* __restrict__ bias;
    __nv_bfloat16 *gh, *gl;
    if (p == 0)      { bias = bq; gh = g_qh; gl = g_ql; }
    else if (p == 1) { bias = bk; gh = g_kh; gl = g_kl; }
    else             { bias = bv; gh = g_vh; gl = g_vl; }
    const __nv_bfloat16* __restrict__ Wh = g_wh + (size_t)p * CC * CC;
    const __nv_bfloat16* __restrict__ Wl = g_wl + (size_t)p * CC * CC;
    const __nv_bfloat16* __restrict__ Hh = g_hh + (size_t)n * CC * WW;
    const __nv_bfloat16* __restrict__ Hl = g_hl + (size_t)n * CC * WW;
    gh += (size_t)n * CC * WW;
    gl += (size_t)n * CC * WW;

    const int o0 = blockIdx.y * 128;     // M
    const int w0 = blockIdx.x * 128;     // N

    const int tid  = threadIdx.x;
    const int wid  = tid >> 5;
    const int lane = tid & 31;
    const int warp_m = wid >> 2;
    const int warp_n = wid & 3;
    const int lr  = lane & 7;
    const int qlo = (lane >> 3) & 1;
    const int qhi = lane >> 4;

    // per-lane ldmatrix base byte offsets (within a buffer)
    const u32 aOff = (u32)((warp_m * 64 + lr + 8 * qlo) * 80 + qhi * 16);
    const u32 bOff = (u32)((lr + 8 * qlo) * 272 + (warp_n * 32 + 8 * qhi) * 2);

    float D[4][4][4];
#pragma unroll
    for (int i = 0; i < 4; i++)
#pragma unroll
        for (int j = 0; j < 4; j++)
#pragma unroll
            for (int r = 0; r < 4; r++) D[i][j][r] = 0.0f;

    // stage chunk kt into buffer bufb
    auto stage = [&](int kt, u32 bufb) {
#pragma unroll
        for (int i = 0; i < 2; i++) {
            const int ia = tid + 256 * i;            // A: 512 chunks of 16B
            const int ra = ia >> 2, ca = ia & 3;     // row 0..127, 16B-col 0..3
            const size_t sa = (size_t)(o0 + ra) * CC + kt + ca * 8;
            cp16(bufb + ra * 80 + ca * 16,          Wh + sa);
            cp16(bufb + 10240 + ra * 80 + ca * 16,  Wl + sa);
            const int ib = tid + 256 * i;            // B: 512 chunks of 16B
            const int rb = ib >> 4, cb = ib & 15;    // row 0..31, 16B-col 0..15
            const size_t sbg = (size_t)(kt + rb) * WW + w0 + cb * 8;
            cp16(bufb + 20480 + rb * 272 + cb * 16, Hh + sbg);
            cp16(bufb + 29184 + rb * 272 + cb * 16, Hl + sbg);
        }
    };

    stage(0, sb);
    CP_COMMIT();

    for (int t = 0; t < 32; t++) {
        const u32 buf = sb + (u32)(t & 1) * 37888u;
        if (t < 31) {
            stage((t + 1) * 32, sb + (u32)((t + 1) & 1) * 37888u);
            CP_COMMIT();
            CP_WAIT1();
        } else {
            CP_WAIT0();
        }
        __syncthreads();

#pragma unroll
        for (int ks = 0; ks < 2; ks++) {
            u32 ah[4][4], al[4][4], bh[4][2], bl[4][2];
#pragma unroll
            for (int i = 0; i < 4; i++) {
                const u32 a = buf + aOff + (u32)(i * 16 * 80 + ks * 32);
                ldsm_x4(ah[i][0], ah[i][1], ah[i][2], ah[i][3], a);
                ldsm_x4(al[i][0], al[i][1], al[i][2], al[i][3], a + 10240);
            }
#pragma unroll
            for (int jp = 0; jp < 2; jp++) {
                const u32 a = buf + 20480 + bOff + (u32)(ks * 16 * 272 + jp * 32);
                ldsm_x4_t(bh[2 * jp][0], bh[2 * jp][1],
                          bh[2 * jp + 1][0], bh[2 * jp + 1][1], a);
                ldsm_x4_t(bl[2 * jp][0], bl[2 * jp][1],
                          bl[2 * jp + 1][0], bl[2 * jp + 1][1], a + 8704);
            }
#pragma unroll
            for (int i = 0; i < 4; i++)
#pragma unroll
                for (int j = 0; j < 4; j++) {
                    mma16816(D[i][j], ah[i], bh[j]);
                    mma16816(D[i][j], ah[i], bl[j]);
                    mma16816(D[i][j], al[i], bh[j]);
                }
        }
        __syncthreads();
    }

    // epilogue: bias + hi/lo split + packed u32 stores
    const int g  = lane >> 2;
    const int tg = lane & 3;
#pragma unroll
    for (int i = 0; i < 4; i++) {
        const int o_lo = o0 + warp_m * 64 + 16 * i + g;
        const int o_hi = o_lo + 8;
        const float b_lo = bias[o_lo];
        const float b_hi = bias[o_hi];
#pragma unroll
        for (int j = 0; j < 4; j++) {
            const int w = w0 + warp_n * 32 + 8 * j + 2 * tg;
            float v0 = D[i][j][0] + b_lo, v1 = D[i][j][1] + b_lo;
            float v2 = D[i][j][2] + b_hi, v3 = D[i][j][3] + b_hi;
            float h0 = bfr(v0), h1 = bfr(v1), h2 = bfr(v2), h3 = bfr(v3);
            *(u32*)&gh[(size_t)o_lo * WW + w] = pack_bf16(h0, h1);
            *(u32*)&gl[(size_t)o_lo * WW + w] = pack_bf16(v0 - h0, v1 - h1);
            *(u32*)&gh[(size_t)o_hi * WW + w] = pack_bf16(h2, h3);
            *(u32*)&gl[(size_t)o_hi * WW + w] = pack_bf16(v2 - h2, v3 - h3);
        }
    }
}

// ---------------------------------------------------------------------------
// Kernel 2: flash attention (unchanged from R10, 274us measured).
// ---------------------------------------------------------------------------
#define ATTN_SMEM 112640

__global__ __launch_bounds__(256, 2) void attn_mma_kernel(
    const float* __restrict__ mask, float* __restrict__ out)
{
    extern __shared__ char smc[];
    const u32 sb = smem_u32(smc);

    const int qb = blockIdx.x;
    const int nh = blockIdx.y;
    const int n  = nh >> 4;
    const int h  = nh & 15;
    const int q0 = qb * 128;

    const size_t cbase = ((size_t)n * CC + h * DD) * WW;
    const __nv_bfloat16* __restrict__ Qh = g_qh + cbase;
    const __nv_bfloat16* __restrict__ Ql = g_ql + cbase;
    const __nv_bfloat16* __restrict__ Kh = g_kh + cbase;
    const __nv_bfloat16* __restrict__ Kl = g_kl + cbase;
    const __nv_bfloat16* __restrict__ Vh = g_vh + cbase;
    const __nv_bfloat16* __restrict__ Vl = g_vl + cbase;

    const int tid  = threadIdx.x;
    const int wid  = tid >> 5;
    const int lane = tid & 31;
    const int qw   = wid * 16;
    const int r    = lane & 7;
    const int b3   = (lane >> 3) & 1;
    const int b4   = lane >> 4;
    const int gr   = lane >> 2;
    const int tg   = lane & 3;

    const u32 qa_off = (u32)((8 * b4 + r) * 272 + (qw + 8 * b3) * 2);  // Q trans
    const u32 ka_off = (u32)((8 * b3 + r) * 144 + (8 * b4) * 2);       // K trans
    const u32 va_off = (u32)((8 * b4 + r) * 144 + (8 * b3) * 2);       // V non-trans

    float* MsP = (float*)(smc + 108544);

#pragma unroll
    for (int i = 0; i < 4; i++) {
        const int idx = tid + 256 * i;
        const int row = idx >> 4, c = idx & 15;
        cp16(sb + row * 272 + c * 16,         Qh + (size_t)row * WW + q0 + c * 8);
        cp16(sb + 17408 + row * 272 + c * 16, Ql + (size_t)row * WW + q0 + c * 8);
    }
    cp16(sb + 108544 + tid * 16, mask + (size_t)n * WW + tid * 4);
#pragma unroll
    for (int i = 0; i < 2; i++) {
        const int idx = tid + 256 * i;
        const int row = idx >> 3, c = idx & 7;
        const size_t so = (size_t)row * WW + c * 8;
        const u32 d = row * 144 + c * 16;
        cp16(sb + 34816 + d, Kh + so);
        cp16(sb + 44032 + d, Kl + so);
        cp16(sb + 71680 + d, Vh + so);
        cp16(sb + 80896 + d, Vl + so);
    }
    CP_COMMIT();

    float sj[8][4], O[8][4];
    float mA = -INFINITY, mB = -INFINITY, lA = 0.0f, lB = 0.0f;
#pragma unroll
    for (int j = 0; j < 8; j++)
#pragma unroll
        for (int q = 0; q < 4; q++) O[j][q] = 0.0f;

    for (int t = 0; t < 16; t++) {
        const int b = t & 1;
        const u32 khb = sb + 34816 + b * 18432;
        const u32 vhb = sb + 71680 + b * 18432;

        if (t + 1 < 16) {
            const int nb = (t + 1) & 1;
            const int k0n = (t + 1) * 64;
#pragma unroll
            for (int i = 0; i < 2; i++) {
                const int idx = tid + 256 * i;
                const int row = idx >> 3, c = idx & 7;
                const size_t so = (size_t)row * WW + k0n + c * 8;
                const u32 d = row * 144 + c * 16;
                cp16(sb + 34816 + nb * 18432 + d, Kh + so);
                cp16(sb + 44032 + nb * 18432 + d, Kl + so);
                cp16(sb + 71680 + nb * 18432 + d, Vh + so);
                cp16(sb + 80896 + nb * 18432 + d, Vl + so);
            }
            CP_COMMIT();
            CP_WAIT1();
        } else {
            CP_WAIT0();
        }
        __syncthreads();

#pragma unroll
        for (int j = 0; j < 8; j++)
#pragma unroll
            for (int q = 0; q < 4; q++) sj[j][q] = 0.0f;

#pragma unroll
        for (int ks = 0; ks < 4; ks++) {
            u32 aH[4], aL[4];
            const u32 qa = sb + ks * 16 * 272 + qa_off;
            ldsm_x4_t(aH[0], aH[1], aH[2], aH[3], qa);
            ldsm_x4_t(aL[0], aL[1], aL[2], aL[3], qa + 17408);
#pragma unroll
            for (int jpg = 0; jpg < 4; jpg++) {
                u32 bh[4], bl[4];
                const u32 ka = khb + ks * 16 * 144 + jpg * 32 + ka_off;
                ldsm_x4_t(bh[0], bh[1], bh[2], bh[3], ka);
                ldsm_x4_t(bl[0], bl[1], bl[2], bl[3], ka + 9216);
                const int jj = 2 * jpg;
                mma16816(sj[jj],     aH, bh);
                mma16816(sj[jj],     aH, bl);
                mma16816(sj[jj],     aL, bh);
                mma16816(sj[jj + 1], aH, bh + 2);
                mma16816(sj[jj + 1], aH, bl + 2);
                mma16816(sj[jj + 1], aL, bh + 2);
            }
        }

        const int k0 = t * 64;
#pragma unroll
        for (int j = 0; j < 8; j++) {
            float2 mm = *(float2*)&MsP[k0 + 8 * j + 2 * tg];
            sj[j][0] = sj[j][0] * 0.125f + mm.x;
            sj[j][1] = sj[j][1] * 0.125f + mm.y;
            sj[j][2] = sj[j][2] * 0.125f + mm.x;
            sj[j][3] = sj[j][3] * 0.125f + mm.y;
        }
        float mxA = -INFINITY, mxB = -INFINITY;
#pragma unroll
        for (int j = 0; j < 8; j++) {
            mxA = fmaxf(mxA, fmaxf(sj[j][0], sj[j][1]));
            mxB = fmaxf(mxB, fmaxf(sj[j][2], sj[j][3]));
        }
        mxA = fmaxf(mxA, __shfl_xor_sync(0xffffffffu, mxA, 1));
        mxA = fmaxf(mxA, __shfl_xor_sync(0xffffffffu, mxA, 2));
        mxB = fmaxf(mxB, __shfl_xor_sync(0xffffffffu, mxB, 1));
        mxB = fmaxf(mxB, __shfl_xor_sync(0xffffffffu, mxB, 2));

        const float nmA = fmaxf(mA, mxA), nmB = fmaxf(mB, mxB);
        const float corrA = __expf(mA - nmA), corrB = __expf(mB - nmB);
        mA = nmA; mB = nmB;

        float rsA = 0.0f, rsB = 0.0f;
#pragma unroll
        for (int j = 0; j < 8; j++) {
            sj[j][0] = __expf(sj[j][0] - mA);
            sj[j][1] = __expf(sj[j][1] - mA);
            sj[j][2] = __expf(sj[j][2] - mB);
            sj[j][3] = __expf(sj[j][3] - mB);
            rsA += sj[j][0] + sj[j][1];
            rsB += sj[j][2] + sj[j][3];
        }
        rsA += __shfl_xor_sync(0xffffffffu, rsA, 1);
        rsA += __shfl_xor_sync(0xffffffffu, rsA, 2);
        rsB += __shfl_xor_sync(0xffffffffu, rsB, 1);
        rsB += __shfl_xor_sync(0xffffffffu, rsB, 2);
        lA = lA * corrA + rsA;
        lB = lB * corrB + rsB;

#pragma unroll
        for (int j = 0; j < 8; j++) {
            O[j][0] *= corrA; O[j][1] *= corrA;
            O[j][2] *= corrB; O[j][3] *= corrB;
        }

#pragma unroll
        for (int ks2 = 0; ks2 < 4; ks2++) {
            const int j0 = 2 * ks2;
            u32 aPH[4], aPL[4];
            {
                float p0 = sj[j0][0], p1 = sj[j0][1], p2 = sj[j0][2], p3 = sj[j0][3];
                float u0 = sj[j0 + 1][0], u1 = sj[j0 + 1][1];
                float u2 = sj[j0 + 1][2], u3 = sj[j0 + 1][3];
                float h0 = bfr(p0), h1 = bfr(p1), h2 = bfr(p2), h3 = bfr(p3);
                float g0 = bfr(u0), g1 = bfr(u1), g2 = bfr(u2), g3 = bfr(u3);
                aPH[0] = pack_bf16(h0, h1); aPH[1] = pack_bf16(h2, h3);
                aPH[2] = pack_bf16(g0, g1); aPH[3] = pack_bf16(g2, g3);
                aPL[0] = pack_bf16(p0 - h0, p1 - h1);
                aPL[1] = pack_bf16(p2 - h2, p3 - h3);
                aPL[2] = pack_bf16(u0 - g0, u1 - g1);
                aPL[3] = pack_bf16(u2 - g2, u3 - g3);
            }
#pragma unroll
            for (int jpg = 0; jpg < 4; jpg++) {
                u32 bh[4], bl[4];
                const u32 va = vhb + jpg * 16 * 144 + ks2 * 32 + va_off;
                ldsm_x4(bh[0], bh[1], bh[2], bh[3], va);
                ldsm_x4(bl[0], bl[1], bl[2], bl[3], va + 9216);
                const int jj = 2 * jpg;
                mma16816(O[jj],     aPH, bh);
                mma16816(O[jj],     aPH, bl);
                mma16816(O[jj],     aPL, bh);
                mma16816(O[jj + 1], aPH, bh + 2);
                mma16816(O[jj + 1], aPH, bl + 2);
                mma16816(O[jj + 1], aPL, bh + 2);
            }
        }
        __syncthreads();
    }

    const float invA = 1.0f / lA, invB = 1.0f / lB;
#pragma unroll
    for (int j = 0; j < 8; j++) {
        O[j][0] *= invA; O[j][1] *= invA;
        O[j][2] *= invB; O[j][3] *= invB;
    }
    float* Obuf = (float*)smc;
    const int r0 = qw + gr, r1 = r0 + 8;
#pragma unroll
    for (int j = 0; j < 8; j++) {
        const int d0 = 8 * j + 2 * tg;
        Obuf[d0 * 128 + r0]       = O[j][0];
        Obuf[(d0 + 1) * 128 + r0] = O[j][1];
        Obuf[d0 * 128 + r1]       = O[j][2];
        Obuf[(d0 + 1) * 128 + r1] = O[j][3];
    }
    __syncthreads();
#pragma unroll
    for (int i = 0; i < 8; i++) {
        const int idx = tid + 256 * i;
        const int row = idx >> 5, c4 = idx & 31;
        *(float4*)&out[((size_t)n * CC + h * DD + row) * WW + q0 + c4 * 4] =
            *(float4*)&Obuf[row * 128 + c4 * 4];
    }
}

// ---------------------------------------------------------------------------
extern "C" void kernel_launch(void* const* d_in, const int* in_sizes, int n_in,
                              void* d_out, int out_size)
{
    const float* hid  = (const float*)d_in[0];
    const float* mask = (const float*)d_in[1];
    const float* wq   = (const float*)d_in[2];
    const float* bq   = (const float*)d_in[3];
    const float* wk   = (const float*)d_in[4];
    const float* bk   = (const float*)d_in[5];
    const float* wv   = (const float*)d_in[6];
    const float* bv   = (const float*)d_in[7];
    float* out = (float*)d_out;

    split_kernel<<<11264, 256>>>(hid, wq, wk, wv);

    cudaFuncSetAttribute(qkv_mma_kernel,
                         cudaFuncAttributeMaxDynamicSharedMemorySize, QKV_SMEM);
    dim3 g1(WW / 128, CC / 128, NB * 3);   // (8, 8, 24)
    qkv_mma_kernel<<<g1, 256, QKV_SMEM>>>(bq, bk, bv);

    cudaFuncSetAttribute(attn_mma_kernel,
                         cudaFuncAttributeMaxDynamicSharedMemorySize, ATTN_SMEM);
    dim3 g2(WW / 128, NB * HH);            // (8, 128)
    attn_mma_kernel<<<g2, 256, ATTN_SMEM>>>(mask, out);
}